// round 3
// baseline (speedup 1.0000x reference)
#include <cuda_runtime.h>
#include <cstdint>
#include <cstddef>

#define EMB 1024
#define SEQ 2048
#define NB  4
#define NH  16
#define HD  64
#define MR  (NB*SEQ)   // 8192 rows

// static device scratch (allocation-guard safe)
__device__ float g_q [(size_t)MR*EMB];
__device__ float g_k [(size_t)MR*EMB];
__device__ float g_v [(size_t)MR*EMB];
__device__ float g_ao[(size_t)MR*EMB];

__device__ __forceinline__ uint32_t f2tf(float f){
    uint32_t u; asm("cvt.rna.tf32.f32 %0, %1;" : "=r"(u) : "f"(f)); return u;
}
__device__ __forceinline__ float ex2f(float x){
    float y; asm("ex2.approx.ftz.f32 %0, %1;" : "=f"(y) : "f"(x)); return y;
}
// D += A*B : m16n8k8 tf32.
// A frag: a0=(g,tg) a1=(g+8,tg) a2=(g,tg+4) a3=(g+8,tg+4)
// B frag: b0=(k=tg,n=g) b1=(k=tg+4,n=g)
// C frag: c0=(g,2tg) c1=(g,2tg+1) c2=(g+8,2tg) c3=(g+8,2tg+1)
__device__ __forceinline__ void mma8(float* d, const uint32_t* a, const uint32_t* b){
    asm volatile(
      "mma.sync.aligned.m16n8k8.row.col.f32.tf32.tf32.f32 "
      "{%0,%1,%2,%3}, {%4,%5,%6,%7}, {%8,%9}, {%0,%1,%2,%3};\n"
      : "+f"(d[0]), "+f"(d[1]), "+f"(d[2]), "+f"(d[3])
      : "r"(a[0]), "r"(a[1]), "r"(a[2]), "r"(a[3]), "r"(b[0]), "r"(b[1]));
}

// ------------------------------------------------------------------
// C[M,N] = A[M,K] @ W[N,K]^T (+bias).  M=8192, N=K=1024.
// grid(8, 64), 256 threads. BM=BN=128, BK=32. Warps 4(m)x2(n) -> 32x64.
// smem stride 36 floats: fragment access bank = (4*row+col)%32 -> conflict-free.
// ------------------------------------------------------------------
__global__ void __launch_bounds__(256) gemm_tf32(
    const float* __restrict__ A, const float* __restrict__ W,
    const float* __restrict__ bias, float* __restrict__ C)
{
    __shared__ uint32_t As[128*36];
    __shared__ uint32_t Bs[128*36];
    const int K = EMB, N = EMB;
    const int tid  = threadIdx.x;
    const int lane = tid & 31, g = lane >> 2, tg = lane & 3;
    const int wid  = tid >> 5;
    const int wm   = (wid & 3) * 32;
    const int wn   = (wid >> 2) * 64;
    const int bm   = blockIdx.y * 128;
    const int bn   = blockIdx.x * 128;

    int r_[4], c4_[4];
    const float4* ap[4]; const float4* bp[4];
    float4 ra[4], rb[4];
#pragma unroll
    for (int i = 0; i < 4; i++){
        int f4 = tid + i*256;            // 1024 float4 per 128x32 tile
        r_[i]  = f4 >> 3;                // 0..127
        c4_[i] = f4 & 7;                 // 0..7
        ap[i] = (const float4*)(A + (size_t)(bm + r_[i])*K + c4_[i]*4);
        bp[i] = (const float4*)(W + (size_t)(bn + r_[i])*K + c4_[i]*4);
        ra[i] = ap[i][0];
        rb[i] = bp[i][0];
    }

    float acc[2][8][4];
#pragma unroll
    for (int mi = 0; mi < 2; mi++)
#pragma unroll
        for (int nf = 0; nf < 8; nf++)
#pragma unroll
            for (int j = 0; j < 4; j++) acc[mi][nf][j] = 0.f;

    const int nk = K / 32;
    for (int kt = 0; kt < nk; kt++){
        // stage -> smem (convert to tf32)
#pragma unroll
        for (int i = 0; i < 4; i++){
            uint32_t* pa = &As[r_[i]*36 + c4_[i]*4];
            pa[0]=f2tf(ra[i].x); pa[1]=f2tf(ra[i].y); pa[2]=f2tf(ra[i].z); pa[3]=f2tf(ra[i].w);
            uint32_t* pb = &Bs[r_[i]*36 + c4_[i]*4];
            pb[0]=f2tf(rb[i].x); pb[1]=f2tf(rb[i].y); pb[2]=f2tf(rb[i].z); pb[3]=f2tf(rb[i].w);
        }
        __syncthreads();
        if (kt + 1 < nk){                 // prefetch next tile into regs
#pragma unroll
            for (int i = 0; i < 4; i++){
                ra[i] = ap[i][(kt+1)*8];
                rb[i] = bp[i][(kt+1)*8];
            }
        }
#pragma unroll
        for (int kk = 0; kk < 32; kk += 8){
            uint32_t af[2][4], bf[8][2];
#pragma unroll
            for (int mi = 0; mi < 2; mi++){
                const uint32_t* p = &As[(wm + mi*16 + g)*36 + kk + tg];
                af[mi][0] = p[0];
                af[mi][1] = p[8*36];
                af[mi][2] = p[4];
                af[mi][3] = p[8*36 + 4];
            }
#pragma unroll
            for (int nf = 0; nf < 8; nf++){
                const uint32_t* p = &Bs[(wn + nf*8 + g)*36 + kk + tg];
                bf[nf][0] = p[0];
                bf[nf][1] = p[4];
            }
#pragma unroll
            for (int mi = 0; mi < 2; mi++)
#pragma unroll
                for (int nf = 0; nf < 8; nf++)
                    mma8(acc[mi][nf], af[mi], bf[nf]);
        }
        __syncthreads();
    }

    // epilogue (+ optional bias)
#pragma unroll
    for (int mi = 0; mi < 2; mi++){
#pragma unroll
        for (int nf = 0; nf < 8; nf++){
            int col  = bn + wn + nf*8 + 2*tg;
            float b0 = bias ? bias[col]   : 0.f;
            float b1 = bias ? bias[col+1] : 0.f;
            int row0 = bm + wm + mi*16 + g;
            float2 v0 = make_float2(acc[mi][nf][0] + b0, acc[mi][nf][1] + b1);
            float2 v1 = make_float2(acc[mi][nf][2] + b0, acc[mi][nf][3] + b1);
            *(float2*)(C + (size_t)row0      *N + col) = v0;
            *(float2*)(C + (size_t)(row0 + 8)*N + col) = v1;
        }
    }
}

// ------------------------------------------------------------------
// Flash attention (causal). grid(32, B*H), 128 threads (4 warps).
// Each block: one (b, h, 64-query tile). Q fragments in registers.
// Ks doubles as Ps (P tile) buffer; Vs holds V transposed [d][s].
// smem stride 68: fragment bank = (4*row+col)%32 -> conflict-free.
// ------------------------------------------------------------------
__global__ void __launch_bounds__(128) attn_kernel(
    const float* __restrict__ Q, const float* __restrict__ K,
    const float* __restrict__ V, float* __restrict__ O)
{
    __shared__ uint32_t Ks[64*68];    // K tile [s][d]; later aliased as P tile
    __shared__ uint32_t Vs[64*68];    // V transposed [d][s]

    const int tid  = threadIdx.x;
    const int lane = tid & 31, g = lane >> 2, tg = lane & 3;
    const int wq   = tid >> 5;                       // warp -> 16 q rows
    const int qt   = gridDim.x - 1 - blockIdx.x;     // heavy blocks first
    const int b    = blockIdx.y >> 4;
    const int h    = blockIdx.y & 15;

    const int qr0 = qt*64 + wq*16 + g;               // this thread's 2 q rows
    const int qr1 = qr0 + 8;

    // Q fragments in registers: qf[ks][4], ks = d/8
    uint32_t qf[8][4];
    {
        const float* Qg0 = Q + ((size_t)(b*SEQ + qr0))*EMB + h*64;
        const float* Qg1 = Q + ((size_t)(b*SEQ + qr1))*EMB + h*64;
#pragma unroll
        for (int ks = 0; ks < 8; ks++){
            int kk = ks*8;
            qf[ks][0] = f2tf(Qg0[kk + tg]);
            qf[ks][1] = f2tf(Qg1[kk + tg]);
            qf[ks][2] = f2tf(Qg0[kk + tg + 4]);
            qf[ks][3] = f2tf(Qg1[kk + tg + 4]);
        }
    }

    float m0 = -1e30f, m1 = -1e30f, l0 = 0.f, l1 = 0.f;
    float o[8][4];
#pragma unroll
    for (int nf = 0; nf < 8; nf++)
#pragma unroll
        for (int j = 0; j < 4; j++) o[nf][j] = 0.f;

    const float cs = 0.125f * 1.44269504088896f;     // 1/sqrt(64) * log2(e)

    for (int jt = 0; jt <= qt; jt++){
        __syncthreads();   // previous P@V done: Ks/Ps and Vs free
        // load K tile -> Ks[s][d], V tile -> Vs[d][s]  (tf32)
#pragma unroll
        for (int i = 0; i < 8; i++){
            int f4 = tid + i*128;       // 1024 float4
            int r  = f4 >> 4;           // s within tile
            int c4 = f4 & 15;           // d/4
            size_t gro = (size_t)(b*SEQ + jt*64 + r)*EMB + h*64 + c4*4;
            float4 kvv = *(const float4*)(K + gro);
            uint32_t* p = &Ks[r*68 + c4*4];
            p[0]=f2tf(kvv.x); p[1]=f2tf(kvv.y); p[2]=f2tf(kvv.z); p[3]=f2tf(kvv.w);
            float4 vvv = *(const float4*)(V + gro);
            Vs[(c4*4+0)*68 + r] = f2tf(vvv.x);
            Vs[(c4*4+1)*68 + r] = f2tf(vvv.y);
            Vs[(c4*4+2)*68 + r] = f2tf(vvv.z);
            Vs[(c4*4+3)*68 + r] = f2tf(vvv.w);
        }
        __syncthreads();

        // S = Q @ K^T  (64x64 per block; 16 rows per warp)
        float s[8][4];
#pragma unroll
        for (int nf = 0; nf < 8; nf++)
#pragma unroll
            for (int j = 0; j < 4; j++) s[nf][j] = 0.f;
#pragma unroll
        for (int ks = 0; ks < 8; ks++){
            int kk = ks*8;
            uint32_t bf[8][2];
#pragma unroll
            for (int nf = 0; nf < 8; nf++){
                const uint32_t* p = &Ks[(nf*8 + g)*68 + kk + tg];
                bf[nf][0] = p[0];
                bf[nf][1] = p[4];
            }
#pragma unroll
            for (int nf = 0; nf < 8; nf++)
                mma8(s[nf], qf[ks], bf[nf]);
        }

        // scale + causal mask + online softmax (exp2 domain)
        float tmax0 = -1e30f, tmax1 = -1e30f;
#pragma unroll
        for (int nf = 0; nf < 8; nf++){
            int jc = jt*64 + nf*8 + 2*tg;
            s[nf][0] = (jc     <= qr0) ? s[nf][0]*cs : -1e30f;
            s[nf][1] = (jc + 1 <= qr0) ? s[nf][1]*cs : -1e30f;
            s[nf][2] = (jc     <= qr1) ? s[nf][2]*cs : -1e30f;
            s[nf][3] = (jc + 1 <= qr1) ? s[nf][3]*cs : -1e30f;
            tmax0 = fmaxf(tmax0, fmaxf(s[nf][0], s[nf][1]));
            tmax1 = fmaxf(tmax1, fmaxf(s[nf][2], s[nf][3]));
        }
        tmax0 = fmaxf(tmax0, __shfl_xor_sync(0xffffffffu, tmax0, 1));
        tmax0 = fmaxf(tmax0, __shfl_xor_sync(0xffffffffu, tmax0, 2));
        tmax1 = fmaxf(tmax1, __shfl_xor_sync(0xffffffffu, tmax1, 1));
        tmax1 = fmaxf(tmax1, __shfl_xor_sync(0xffffffffu, tmax1, 2));
        float mn0 = fmaxf(m0, tmax0);
        float mn1 = fmaxf(m1, tmax1);
        float a0  = ex2f(m0 - mn0);
        float a1  = ex2f(m1 - mn1);
        float rs0 = 0.f, rs1 = 0.f;
#pragma unroll
        for (int nf = 0; nf < 8; nf++){
            s[nf][0] = ex2f(s[nf][0] - mn0);
            s[nf][1] = ex2f(s[nf][1] - mn0);
            s[nf][2] = ex2f(s[nf][2] - mn1);
            s[nf][3] = ex2f(s[nf][3] - mn1);
            rs0 += s[nf][0] + s[nf][1];
            rs1 += s[nf][2] + s[nf][3];
        }
        rs0 += __shfl_xor_sync(0xffffffffu, rs0, 1);
        rs0 += __shfl_xor_sync(0xffffffffu, rs0, 2);
        rs1 += __shfl_xor_sync(0xffffffffu, rs1, 1);
        rs1 += __shfl_xor_sync(0xffffffffu, rs1, 2);
        l0 = l0*a0 + rs0;
        l1 = l1*a1 + rs1;
        m0 = mn0; m1 = mn1;
#pragma unroll
        for (int nf = 0; nf < 8; nf++){
            o[nf][0] *= a0; o[nf][1] *= a0;
            o[nf][2] *= a1; o[nf][3] *= a1;
        }

        // store P into Ks buffer (all warps must be done reading Ks first)
        __syncthreads();
        {
            int pr0 = wq*16 + g;
#pragma unroll
            for (int nf = 0; nf < 8; nf++){
                uint32_t* p0 = &Ks[(pr0    )*68 + nf*8 + 2*tg];
                uint32_t* p1 = &Ks[(pr0 + 8)*68 + nf*8 + 2*tg];
                p0[0] = f2tf(s[nf][0]); p0[1] = f2tf(s[nf][1]);
                p1[0] = f2tf(s[nf][2]); p1[1] = f2tf(s[nf][3]);
            }
        }
        __syncwarp();   // P rows are warp-private: warp-level ordering suffices

        // O += P @ V   (A = Ps rows wq*16.., B = Vs[d][s])
#pragma unroll
        for (int ks = 0; ks < 8; ks++){
            int kk = ks*8;
            uint32_t af[4];
            const uint32_t* pa0 = &Ks[(wq*16 + g    )*68 + kk + tg];
            const uint32_t* pa1 = &Ks[(wq*16 + g + 8)*68 + kk + tg];
            af[0] = pa0[0]; af[1] = pa1[0]; af[2] = pa0[4]; af[3] = pa1[4];
            uint32_t bf[8][2];
#pragma unroll
            for (int nf = 0; nf < 8; nf++){
                const uint32_t* p = &Vs[(nf*8 + g)*68 + kk + tg];
                bf[nf][0] = p[0];
                bf[nf][1] = p[4];
            }
#pragma unroll
            for (int nf = 0; nf < 8; nf++)
                mma8(o[nf], af, bf[nf]);
        }
    }

    // write out: O[b, s, h*64 + d]
    float inv0 = 1.f / l0;
    float inv1 = 1.f / l1;
#pragma unroll
    for (int nf = 0; nf < 8; nf++){
        int col = h*64 + nf*8 + 2*tg;
        float2 v0 = make_float2(o[nf][0]*inv0, o[nf][1]*inv0);
        float2 v1 = make_float2(o[nf][2]*inv1, o[nf][3]*inv1);
        *(float2*)(O + (size_t)(b*SEQ + qr0)*EMB + col) = v0;
        *(float2*)(O + (size_t)(b*SEQ + qr1)*EMB + col) = v1;
    }
}

// ------------------------------------------------------------------
extern "C" void kernel_launch(void* const* d_in, const int* in_sizes, int n_in,
                              void* d_out, int out_size)
{
    const float* x  = (const float*)d_in[0];
    const float* Wq = (const float*)d_in[1];
    const float* Wk = (const float*)d_in[2];
    const float* Wv = (const float*)d_in[3];
    const float* Wo = (const float*)d_in[4];
    const float* bo = (const float*)d_in[5];
    float* out = (float*)d_out;

    float *q, *k, *v, *ao;
    cudaGetSymbolAddress((void**)&q,  g_q);
    cudaGetSymbolAddress((void**)&k,  g_k);
    cudaGetSymbolAddress((void**)&v,  g_v);
    cudaGetSymbolAddress((void**)&ao, g_ao);

    dim3 gg(8, 64);           // N/128 x M/128
    gemm_tf32<<<gg, 256>>>(x, Wq, nullptr, q);
    gemm_tf32<<<gg, 256>>>(x, Wk, nullptr, k);
    gemm_tf32<<<gg, 256>>>(x, Wv, nullptr, v);

    dim3 ga(SEQ/64, NB*NH);   // 32 x 64
    attn_kernel<<<ga, 128>>>(q, k, v, ao);

    gemm_tf32<<<gg, 256>>>(ao, Wo, bo, out);
}

// round 4
// speedup vs baseline: 1.0670x; 1.0670x over previous
#include <cuda_runtime.h>
#include <cstdint>
#include <cstddef>

#define EMB 1024
#define SEQ 2048
#define NB  4
#define NH  16
#define MR  (NB*SEQ)   // 8192 rows

// static device scratch (allocation-guard safe)
__device__ float g_q [(size_t)MR*EMB];
__device__ float g_k [(size_t)MR*EMB];
__device__ float g_v [(size_t)MR*EMB];
__device__ float g_ao[(size_t)MR*EMB];

__device__ __forceinline__ uint32_t f2tf(float f){
    uint32_t u; asm("cvt.rna.tf32.f32 %0, %1;" : "=r"(u) : "f"(f)); return u;
}
__device__ __forceinline__ float ex2f(float x){
    float y; asm("ex2.approx.ftz.f32 %0, %1;" : "=f"(y) : "f"(x)); return y;
}
// D += A*B : m16n8k8 tf32.
// A frag: a0=(g,tg) a1=(g+8,tg) a2=(g,tg+4) a3=(g+8,tg+4)
// B frag: b0=(k=tg,n=g) b1=(k=tg+4,n=g)
// C frag: c0=(g,2tg) c1=(g,2tg+1) c2=(g+8,2tg) c3=(g+8,2tg+1)
__device__ __forceinline__ void mma8(float* d, const uint32_t* a, const uint32_t* b){
    asm volatile(
      "mma.sync.aligned.m16n8k8.row.col.f32.tf32.tf32.f32 "
      "{%0,%1,%2,%3}, {%4,%5,%6,%7}, {%8,%9}, {%0,%1,%2,%3};\n"
      : "+f"(d[0]), "+f"(d[1]), "+f"(d[2]), "+f"(d[3])
      : "r"(a[0]), "r"(a[1]), "r"(a[2]), "r"(a[3]), "r"(b[0]), "r"(b[1]));
}

// ------------------------------------------------------------------
// C[M,N] = A[M,K] @ W[N,K]^T (+bias).  M=8192, N=K=1024.
// grid(8, 64), 256 threads. BM=BN=128, BK=16, DOUBLE-BUFFERED smem.
// smem stride 20 words: fragment bank = (20*row + col) % 32, with
// 20*g mod 32 = {0,20,8,28,16,4,24,12} distinct -> conflict-free.
// One __syncthreads per k-step; global prefetch overlaps MMA.
// ------------------------------------------------------------------
__global__ void __launch_bounds__(256) gemm_tf32(
    const float* __restrict__ A, const float* __restrict__ W,
    const float* __restrict__ bias, float* __restrict__ C)
{
    __shared__ uint32_t smA[2][128*20];
    __shared__ uint32_t smB[2][128*20];

    const int tid  = threadIdx.x;
    const int lane = tid & 31, g = lane >> 2, tg = lane & 3;
    const int wid  = tid >> 5;
    const int wm   = (wid & 3) * 32;
    const int wn   = (wid >> 2) * 64;
    const int bm   = blockIdx.y * 128;
    const int bn   = blockIdx.x * 128;

    // staging mapping: 128x16 tile = 512 float4; thread handles rows r, r+64
    const int r  = tid >> 2;        // 0..63
    const int c4 = tid & 3;         // 0..3
    const float* Ab = A + (size_t)(bm + r)*EMB + c4*4;
    const float* Wb = W + (size_t)(bn + r)*EMB + c4*4;

    float4 ra0, ra1, rb0, rb1;
    ra0 = *(const float4*)(Ab);
    ra1 = *(const float4*)(Ab + 64*EMB);
    rb0 = *(const float4*)(Wb);
    rb1 = *(const float4*)(Wb + 64*EMB);

    float acc[2][8][4];
#pragma unroll
    for (int mi = 0; mi < 2; mi++)
#pragma unroll
        for (int nf = 0; nf < 8; nf++)
#pragma unroll
            for (int j = 0; j < 4; j++) acc[mi][nf][j] = 0.f;

    // store stage 0
    {
        uint32_t* pa0 = &smA[0][r*20 + c4*4];
        uint32_t* pa1 = &smA[0][(r+64)*20 + c4*4];
        uint32_t* pb0 = &smB[0][r*20 + c4*4];
        uint32_t* pb1 = &smB[0][(r+64)*20 + c4*4];
        pa0[0]=f2tf(ra0.x); pa0[1]=f2tf(ra0.y); pa0[2]=f2tf(ra0.z); pa0[3]=f2tf(ra0.w);
        pa1[0]=f2tf(ra1.x); pa1[1]=f2tf(ra1.y); pa1[2]=f2tf(ra1.z); pa1[3]=f2tf(ra1.w);
        pb0[0]=f2tf(rb0.x); pb0[1]=f2tf(rb0.y); pb0[2]=f2tf(rb0.z); pb0[3]=f2tf(rb0.w);
        pb1[0]=f2tf(rb1.x); pb1[1]=f2tf(rb1.y); pb1[2]=f2tf(rb1.z); pb1[3]=f2tf(rb1.w);
    }

    const int nk = EMB / 16;   // 64
    for (int kt = 0; kt < nk; kt++){
        __syncthreads();
        const int cur = kt & 1;
        if (kt + 1 < nk){
            ra0 = *(const float4*)(Ab + (kt+1)*16);
            ra1 = *(const float4*)(Ab + (kt+1)*16 + 64*EMB);
            rb0 = *(const float4*)(Wb + (kt+1)*16);
            rb1 = *(const float4*)(Wb + (kt+1)*16 + 64*EMB);
        }
        const uint32_t* SA = smA[cur];
        const uint32_t* SB = smB[cur];
#pragma unroll
        for (int kk = 0; kk < 16; kk += 8){
            uint32_t af[2][4], bf[8][2];
#pragma unroll
            for (int mi = 0; mi < 2; mi++){
                const uint32_t* p = &SA[(wm + mi*16 + g)*20 + kk + tg];
                af[mi][0] = p[0];
                af[mi][1] = p[8*20];
                af[mi][2] = p[4];
                af[mi][3] = p[8*20 + 4];
            }
#pragma unroll
            for (int nf = 0; nf < 8; nf++){
                const uint32_t* p = &SB[(wn + nf*8 + g)*20 + kk + tg];
                bf[nf][0] = p[0];
                bf[nf][1] = p[4];
            }
#pragma unroll
            for (int mi = 0; mi < 2; mi++)
#pragma unroll
                for (int nf = 0; nf < 8; nf++)
                    mma8(acc[mi][nf], af[mi], bf[nf]);
        }
        if (kt + 1 < nk){
            const int nxt = cur ^ 1;
            uint32_t* pa0 = &smA[nxt][r*20 + c4*4];
            uint32_t* pa1 = &smA[nxt][(r+64)*20 + c4*4];
            uint32_t* pb0 = &smB[nxt][r*20 + c4*4];
            uint32_t* pb1 = &smB[nxt][(r+64)*20 + c4*4];
            pa0[0]=f2tf(ra0.x); pa0[1]=f2tf(ra0.y); pa0[2]=f2tf(ra0.z); pa0[3]=f2tf(ra0.w);
            pa1[0]=f2tf(ra1.x); pa1[1]=f2tf(ra1.y); pa1[2]=f2tf(ra1.z); pa1[3]=f2tf(ra1.w);
            pb0[0]=f2tf(rb0.x); pb0[1]=f2tf(rb0.y); pb0[2]=f2tf(rb0.z); pb0[3]=f2tf(rb0.w);
            pb1[0]=f2tf(rb1.x); pb1[1]=f2tf(rb1.y); pb1[2]=f2tf(rb1.z); pb1[3]=f2tf(rb1.w);
        }
    }

    // epilogue (+ optional bias)
#pragma unroll
    for (int mi = 0; mi < 2; mi++){
#pragma unroll
        for (int nf = 0; nf < 8; nf++){
            int col  = bn + wn + nf*8 + 2*tg;
            float b0 = bias ? bias[col]   : 0.f;
            float b1 = bias ? bias[col+1] : 0.f;
            int row0 = bm + wm + mi*16 + g;
            float2 v0 = make_float2(acc[mi][nf][0] + b0, acc[mi][nf][1] + b1);
            float2 v1 = make_float2(acc[mi][nf][2] + b0, acc[mi][nf][3] + b1);
            *(float2*)(C + (size_t)row0      *EMB + col) = v0;
            *(float2*)(C + (size_t)(row0 + 8)*EMB + col) = v1;
        }
    }
}

// ------------------------------------------------------------------
// Flash attention v2 (causal). grid(16, B*H), 128 threads (4 warps).
// q-tile 128 per block; each warp owns 32 q rows (2 m-fragments), so
// every K/V B-fragment load feeds 2 MMAs (2x reuse vs R3).
// Q in smem; K [s][d]; V transposed [d][s] via conflict-free STS.128.
// P never hits smem: S C-frags -> PV A-frags via intra-warp shuffles.
// Dynamic smem 256*68*4 = 69632 B.
// ------------------------------------------------------------------
__global__ void __launch_bounds__(128) attn_kernel(
    const float* __restrict__ Q, const float* __restrict__ K,
    const float* __restrict__ V, float* __restrict__ O)
{
    extern __shared__ uint32_t dyn[];
    uint32_t* Qs = dyn;              // 128 x 68
    uint32_t* Ks = dyn + 128*68;     // 64 x 68   [s][d]
    uint32_t* Vs = dyn + 192*68;     // 64 x 68   [d][s]

    const int tid  = threadIdx.x;
    const int lane = tid & 31, g = lane >> 2, tg = lane & 3;
    const int wq   = tid >> 5;
    const int qt   = gridDim.x - 1 - blockIdx.x;    // heavy blocks first
    const int b    = blockIdx.y >> 4;
    const int h    = blockIdx.y & 15;
    const int qbase = qt * 128;
    const float cs = 0.125f * 1.44269504088896f;    // 1/sqrt(64)*log2(e)

    // ---- load Q tile -> Qs (tf32), STS.128-friendly, conflict-free
    const float* Qg = Q + (size_t)(b*SEQ + qbase)*EMB + h*64;
#pragma unroll
    for (int i = 0; i < 16; i++){
        int f4 = tid + i*128;
        int r = f4 >> 4, c4 = f4 & 15;
        float4 qv = *(const float4*)(Qg + (size_t)r*EMB + c4*4);
        uint4 pk = make_uint4(f2tf(qv.x), f2tf(qv.y), f2tf(qv.z), f2tf(qv.w));
        *(uint4*)&Qs[r*68 + c4*4] = pk;
    }

    float mrow[4], lrow[4];
#pragma unroll
    for (int i = 0; i < 4; i++){ mrow[i] = -1e30f; lrow[i] = 0.f; }
    float o[2][8][4];
#pragma unroll
    for (int mi = 0; mi < 2; mi++)
#pragma unroll
        for (int nf = 0; nf < 8; nf++)
#pragma unroll
            for (int j = 0; j < 4; j++) o[mi][nf][j] = 0.f;

    const float* Kg = K + (size_t)(b*SEQ)*EMB + h*64;
    const float* Vg = V + (size_t)(b*SEQ)*EMB + h*64;

    const int src0 = (lane & 28) | (tg >> 1);   // shuffle sources for P relayout
    const int src1 = src0 + 2;
    const bool odd = tg & 1;

    const int njt = 2*qt + 2;
    for (int jt = 0; jt < njt; jt++){
        __syncthreads();   // Ks/Vs free (and Q store visible on iter 0)
        // K tile -> Ks[s][d]
#pragma unroll
        for (int i = 0; i < 8; i++){
            int f4 = tid + i*128;
            int r = f4 >> 4, c4 = f4 & 15;
            float4 kv = *(const float4*)(Kg + (size_t)(jt*64 + r)*EMB + c4*4);
            uint4 pk = make_uint4(f2tf(kv.x), f2tf(kv.y), f2tf(kv.z), f2tf(kv.w));
            *(uint4*)&Ks[r*68 + c4*4] = pk;
        }
        // V tile -> Vs[d][s] (transposed). d across lanes => coalesced LDG.32,
        // STS.128 of 4 consecutive s => conflict-free store.
#pragma unroll
        for (int i = 0; i < 8; i++){
            int u  = wq + i*4;              // 0..31, unique per (warp, i)
            int s0 = (u & 15) * 4;
            int d  = (u >> 4) * 32 + lane;
            const float* vb = Vg + (size_t)(jt*64 + s0)*EMB + d;
            float v0 = vb[0];
            float v1 = vb[EMB];
            float v2 = vb[2*EMB];
            float v3 = vb[3*EMB];
            uint4 pk = make_uint4(f2tf(v0), f2tf(v1), f2tf(v2), f2tf(v3));
            *(uint4*)&Vs[d*68 + s0] = pk;
        }
        __syncthreads();

        // ---- S = Q @ K^T : 32 q-rows x 64 keys per warp
        float sacc[2][8][4];
#pragma unroll
        for (int mi = 0; mi < 2; mi++)
#pragma unroll
            for (int nf = 0; nf < 8; nf++)
#pragma unroll
                for (int j = 0; j < 4; j++) sacc[mi][nf][j] = 0.f;
#pragma unroll
        for (int ks = 0; ks < 8; ks++){
            int kk = ks*8;
            uint32_t aq[2][4];
#pragma unroll
            for (int mi = 0; mi < 2; mi++){
                const uint32_t* p = &Qs[(wq*32 + mi*16 + g)*68 + kk + tg];
                aq[mi][0] = p[0];
                aq[mi][1] = p[8*68];
                aq[mi][2] = p[4];
                aq[mi][3] = p[8*68 + 4];
            }
            uint32_t bk[8][2];
#pragma unroll
            for (int nf = 0; nf < 8; nf++){
                const uint32_t* p = &Ks[(nf*8 + g)*68 + kk + tg];
                bk[nf][0] = p[0];
                bk[nf][1] = p[4];
            }
#pragma unroll
            for (int mi = 0; mi < 2; mi++)
#pragma unroll
                for (int nf = 0; nf < 8; nf++)
                    mma8(sacc[mi][nf], aq[mi], bk[nf]);
        }

        // ---- scale + (diagonal-only) causal mask + online softmax
        const bool need_mask = (jt >= 2*qt);
#pragma unroll
        for (int mi = 0; mi < 2; mi++){
            int q0 = qbase + wq*32 + mi*16 + g;
            int q1 = q0 + 8;
            float tm0 = -1e30f, tm1 = -1e30f;
#pragma unroll
            for (int nf = 0; nf < 8; nf++){
                float* s = sacc[mi][nf];
                if (need_mask){
                    int jc = jt*64 + nf*8 + 2*tg;
                    s[0] = (jc     <= q0) ? s[0]*cs : -1e30f;
                    s[1] = (jc + 1 <= q0) ? s[1]*cs : -1e30f;
                    s[2] = (jc     <= q1) ? s[2]*cs : -1e30f;
                    s[3] = (jc + 1 <= q1) ? s[3]*cs : -1e30f;
                } else {
                    s[0] *= cs; s[1] *= cs; s[2] *= cs; s[3] *= cs;
                }
                tm0 = fmaxf(tm0, fmaxf(s[0], s[1]));
                tm1 = fmaxf(tm1, fmaxf(s[2], s[3]));
            }
            tm0 = fmaxf(tm0, __shfl_xor_sync(0xffffffffu, tm0, 1));
            tm0 = fmaxf(tm0, __shfl_xor_sync(0xffffffffu, tm0, 2));
            tm1 = fmaxf(tm1, __shfl_xor_sync(0xffffffffu, tm1, 1));
            tm1 = fmaxf(tm1, __shfl_xor_sync(0xffffffffu, tm1, 2));
            float mn0 = fmaxf(mrow[mi*2],     tm0);
            float mn1 = fmaxf(mrow[mi*2 + 1], tm1);
            float a0  = ex2f(mrow[mi*2]     - mn0);
            float a1  = ex2f(mrow[mi*2 + 1] - mn1);
            float rs0 = 0.f, rs1 = 0.f;
#pragma unroll
            for (int nf = 0; nf < 8; nf++){
                float* s = sacc[mi][nf];
                s[0] = ex2f(s[0] - mn0);
                s[1] = ex2f(s[1] - mn0);
                s[2] = ex2f(s[2] - mn1);
                s[3] = ex2f(s[3] - mn1);
                rs0 += s[0] + s[1];
                rs1 += s[2] + s[3];
            }
            rs0 += __shfl_xor_sync(0xffffffffu, rs0, 1);
            rs0 += __shfl_xor_sync(0xffffffffu, rs0, 2);
            rs1 += __shfl_xor_sync(0xffffffffu, rs1, 1);
            rs1 += __shfl_xor_sync(0xffffffffu, rs1, 2);
            lrow[mi*2]     = lrow[mi*2]*a0     + rs0;
            lrow[mi*2 + 1] = lrow[mi*2 + 1]*a1 + rs1;
            mrow[mi*2]     = mn0;
            mrow[mi*2 + 1] = mn1;
#pragma unroll
            for (int nf = 0; nf < 8; nf++){
                o[mi][nf][0] *= a0; o[mi][nf][1] *= a0;
                o[mi][nf][2] *= a1; o[mi][nf][3] *= a1;
            }
        }

        // ---- O += P @ V : A-frags built from sacc via shuffles (no smem P)
#pragma unroll
        for (int ks = 0; ks < 8; ks++){
            int kk = ks*8;
            uint32_t bv[8][2];
#pragma unroll
            for (int nf = 0; nf < 8; nf++){
                const uint32_t* p = &Vs[(nf*8 + g)*68 + kk + tg];
                bv[nf][0] = p[0];
                bv[nf][1] = p[4];
            }
#pragma unroll
            for (int mi = 0; mi < 2; mi++){
                float x0 = sacc[mi][ks][0], x1 = sacc[mi][ks][1];
                float x2 = sacc[mi][ks][2], x3 = sacc[mi][ks][3];
                float y0 = __shfl_sync(0xffffffffu, x0, src0);
                float y1 = __shfl_sync(0xffffffffu, x1, src0);
                float y2 = __shfl_sync(0xffffffffu, x2, src0);
                float y3 = __shfl_sync(0xffffffffu, x3, src0);
                float z0 = __shfl_sync(0xffffffffu, x0, src1);
                float z1 = __shfl_sync(0xffffffffu, x1, src1);
                float z2 = __shfl_sync(0xffffffffu, x2, src1);
                float z3 = __shfl_sync(0xffffffffu, x3, src1);
                uint32_t av[4];
                av[0] = f2tf(odd ? y1 : y0);
                av[1] = f2tf(odd ? y3 : y2);
                av[2] = f2tf(odd ? z1 : z0);
                av[3] = f2tf(odd ? z3 : z2);
#pragma unroll
                for (int nf = 0; nf < 8; nf++)
                    mma8(o[mi][nf], av, bv[nf]);
            }
        }
    }

    // ---- epilogue: normalize and write O[b, s, h*64 + d]
#pragma unroll
    for (int mi = 0; mi < 2; mi++){
        float i0 = 1.f / lrow[mi*2];
        float i1 = 1.f / lrow[mi*2 + 1];
        size_t q0 = (size_t)(b*SEQ + qbase + wq*32 + mi*16 + g);
#pragma unroll
        for (int nf = 0; nf < 8; nf++){
            int col = h*64 + nf*8 + 2*tg;
            float2 v0 = make_float2(o[mi][nf][0]*i0, o[mi][nf][1]*i0);
            float2 v1 = make_float2(o[mi][nf][2]*i1, o[mi][nf][3]*i1);
            *(float2*)(O + q0*EMB + col)       = v0;
            *(float2*)(O + (q0 + 8)*EMB + col) = v1;
        }
    }
}

#define ATTN_SMEM (256*68*4)

// ------------------------------------------------------------------
extern "C" void kernel_launch(void* const* d_in, const int* in_sizes, int n_in,
                              void* d_out, int out_size)
{
    const float* x  = (const float*)d_in[0];
    const float* Wq = (const float*)d_in[1];
    const float* Wk = (const float*)d_in[2];
    const float* Wv = (const float*)d_in[3];
    const float* Wo = (const float*)d_in[4];
    const float* bo = (const float*)d_in[5];
    float* out = (float*)d_out;

    float *q, *k, *v, *ao;
    cudaGetSymbolAddress((void**)&q,  g_q);
    cudaGetSymbolAddress((void**)&k,  g_k);
    cudaGetSymbolAddress((void**)&v,  g_v);
    cudaGetSymbolAddress((void**)&ao, g_ao);

    cudaFuncSetAttribute(attn_kernel,
                         cudaFuncAttributeMaxDynamicSharedMemorySize, ATTN_SMEM);

    dim3 gg(8, 64);            // N/128 x M/128
    gemm_tf32<<<gg, 256>>>(x, Wq, nullptr, q);
    gemm_tf32<<<gg, 256>>>(x, Wk, nullptr, k);
    gemm_tf32<<<gg, 256>>>(x, Wv, nullptr, v);

    dim3 ga(SEQ/128, NB*NH);   // 16 x 64
    attn_kernel<<<ga, 128, ATTN_SMEM>>>(q, k, v, ao);

    gemm_tf32<<<gg, 256>>>(ao, Wo, bo, out);
}

// round 5
// speedup vs baseline: 1.5042x; 1.4098x over previous
#include <cuda_runtime.h>
#include <cstdint>
#include <cstddef>

#define EMB 1024
#define SEQ 2048
#define NB  4
#define NH  16
#define MR  (NB*SEQ)   // 8192 rows

// static device scratch (allocation-guard safe)
__device__ float g_q [(size_t)MR*EMB];
__device__ float g_k [(size_t)MR*EMB];
__device__ float g_v [(size_t)MR*EMB];
__device__ float g_ao[(size_t)MR*EMB];
__device__ float g_xc[(size_t)MR*EMB];          // x pre-converted to tf32
__device__ float g_wq[(size_t)EMB*EMB];
__device__ float g_wk[(size_t)EMB*EMB];
__device__ float g_wv[(size_t)EMB*EMB];
__device__ float g_wo[(size_t)EMB*EMB];

__device__ __forceinline__ uint32_t f2tf(float f){
    uint32_t u; asm("cvt.rna.tf32.f32 %0, %1;" : "=r"(u) : "f"(f)); return u;
}
__device__ __forceinline__ float ex2f(float x){
    float y; asm("ex2.approx.ftz.f32 %0, %1;" : "=f"(y) : "f"(x)); return y;
}
// D += A*B : m16n8k8 tf32.
// A frag: a0=(g,tg) a1=(g+8,tg) a2=(g,tg+4) a3=(g+8,tg+4)
// B frag: b0=(k=tg,n=g) b1=(k=tg+4,n=g)
// C frag: c0=(g,2tg) c1=(g,2tg+1) c2=(g+8,2tg) c3=(g+8,2tg+1)
__device__ __forceinline__ void mma8(float* d, const uint32_t* a, const uint32_t* b){
    asm volatile(
      "mma.sync.aligned.m16n8k8.row.col.f32.tf32.tf32.f32 "
      "{%0,%1,%2,%3}, {%4,%5,%6,%7}, {%8,%9}, {%0,%1,%2,%3};\n"
      : "+f"(d[0]), "+f"(d[1]), "+f"(d[2]), "+f"(d[3])
      : "r"(a[0]), "r"(a[1]), "r"(a[2]), "r"(a[3]), "r"(b[0]), "r"(b[1]));
}
// ldmatrix x4: 4 m8n8.b16 units = one 16x8 (A) tf32 frag or two k8n8 (B) frags
__device__ __forceinline__ void ldsm4(uint32_t* r, uint32_t saddr){
    asm volatile("ldmatrix.sync.aligned.m8n8.x4.shared.b16 {%0,%1,%2,%3}, [%4];"
        : "=r"(r[0]), "=r"(r[1]), "=r"(r[2]), "=r"(r[3]) : "r"(saddr));
}
__device__ __forceinline__ void cpa16(uint32_t saddr, const void* g){
    asm volatile("cp.async.ca.shared.global [%0], [%1], 16;" :: "r"(saddr), "l"(g));
}
__device__ __forceinline__ void cpa_commit(){ asm volatile("cp.async.commit_group;"); }
__device__ __forceinline__ void cpa_wait0(){ asm volatile("cp.async.wait_group 0;"); }
__device__ __forceinline__ void cpa_wait1(){ asm volatile("cp.async.wait_group 1;"); }

// ------------------------------------------------------------------
// elementwise tf32 pre-round (rna) : dst = tf32(src), float4 vectorized
// ------------------------------------------------------------------
__global__ void __launch_bounds__(256) cvt_tf32_k(
    const float4* __restrict__ src, float4* __restrict__ dst, int n4)
{
    int i = blockIdx.x*256 + threadIdx.x;
    if (i < n4){
        float4 v = src[i];
        float4 o;
        o.x = __uint_as_float(f2tf(v.x));
        o.y = __uint_as_float(f2tf(v.y));
        o.z = __uint_as_float(f2tf(v.z));
        o.w = __uint_as_float(f2tf(v.w));
        dst[i] = o;
    }
}

// ------------------------------------------------------------------
// C[M,N] = A[M,K] @ W[N,K]^T (+bias). Inputs pre-rounded to tf32.
// Block 128(m) x 256(n), BK=32, 256 thr, warps 2(m)x4(n) -> 64x64 tiles.
// cp.async double-buffered smem, ldmatrix fragment loads, no cvt in loop.
// smem stride 36 words: rows r..r+7 hit 16B-groups 4r mod 32 (distinct).
// ------------------------------------------------------------------
__device__ __forceinline__ void gemm_body(
    const float* __restrict__ A, const float* __restrict__ W,
    const float* __restrict__ bias, float* __restrict__ C, int cvt_out)
{
    extern __shared__ uint32_t sh[];
    const int SAW = 128*36, STG = SAW + 256*36;
    const uint32_t sbase = (uint32_t)__cvta_generic_to_shared(sh);

    const int tid  = threadIdx.x;
    const int lane = tid & 31, g = lane >> 2, tg = lane & 3;
    const int wid  = tid >> 5;
    const int wm   = (wid & 1) * 64;
    const int wn   = (wid >> 1) * 64;
    const int bm   = blockIdx.y * 128;
    const int bn   = blockIdx.x * 256;

    const int alr = lane & 15, alk = (lane >> 4) * 4;                 // A ldsm lane map
    const int blr = (lane & 7) + ((lane >> 4) << 3), blk = ((lane >> 3) & 1) * 4; // B

    const float* Ag = A + (size_t)bm*EMB;
    const float* Wg = W + (size_t)bn*EMB;

    float acc[4][8][4];
#pragma unroll
    for (int mi = 0; mi < 4; mi++)
#pragma unroll
        for (int t = 0; t < 8; t++)
#pragma unroll
            for (int j = 0; j < 4; j++) acc[mi][t][j] = 0.f;

    auto stage = [&](int kt, int s){
        const uint32_t sa = sbase + (uint32_t)(s*STG)*4;
        const uint32_t sb = sa + (uint32_t)SAW*4;
#pragma unroll
        for (int i = 0; i < 4; i++){               // A: 128x32 = 1024 chunks
            int id = tid + i*256, r = id >> 3, c = id & 7;
            cpa16(sa + (uint32_t)(r*36 + c*4)*4, Ag + (size_t)r*EMB + kt*32 + c*4);
        }
#pragma unroll
        for (int i = 0; i < 8; i++){               // B: 256x32 = 2048 chunks
            int id = tid + i*256, r = id >> 3, c = id & 7;
            cpa16(sb + (uint32_t)(r*36 + c*4)*4, Wg + (size_t)r*EMB + kt*32 + c*4);
        }
        cpa_commit();
    };

    stage(0, 0);
    const int nk = EMB/32;   // 32
    for (int kt = 0; kt < nk; kt++){
        const int cur = kt & 1;
        if (kt + 1 < nk){ stage(kt+1, cur^1); cpa_wait1(); }
        else            { cpa_wait0(); }
        __syncthreads();
        const uint32_t sa = sbase + (uint32_t)(cur*STG)*4;
        const uint32_t sb = sa + (uint32_t)SAW*4;
#pragma unroll
        for (int kk = 0; kk < 32; kk += 8){
            uint32_t af[4][4], bf[4][4];
#pragma unroll
            for (int mi = 0; mi < 4; mi++)
                ldsm4(af[mi], sa + (uint32_t)((wm + mi*16 + alr)*36 + kk + alk)*4);
#pragma unroll
            for (int p = 0; p < 4; p++)
                ldsm4(bf[p], sb + (uint32_t)((wn + p*16 + blr)*36 + kk + blk)*4);
#pragma unroll
            for (int mi = 0; mi < 4; mi++)
#pragma unroll
                for (int p = 0; p < 4; p++){
                    mma8(acc[mi][2*p],   af[mi], &bf[p][0]);
                    mma8(acc[mi][2*p+1], af[mi], &bf[p][2]);
                }
        }
        __syncthreads();
    }

    // epilogue (+ optional bias, optional tf32 pre-round of output)
#pragma unroll
    for (int mi = 0; mi < 4; mi++){
#pragma unroll
        for (int t = 0; t < 8; t++){
            int col  = bn + wn + t*8 + 2*tg;
            int row0 = bm + wm + mi*16 + g;
            float b0 = bias ? bias[col]   : 0.f;
            float b1 = bias ? bias[col+1] : 0.f;
            float v00 = acc[mi][t][0] + b0, v01 = acc[mi][t][1] + b1;
            float v10 = acc[mi][t][2] + b0, v11 = acc[mi][t][3] + b1;
            float2 u0, u1;
            if (cvt_out){
                u0 = make_float2(__uint_as_float(f2tf(v00)), __uint_as_float(f2tf(v01)));
                u1 = make_float2(__uint_as_float(f2tf(v10)), __uint_as_float(f2tf(v11)));
            } else {
                u0 = make_float2(v00, v01);
                u1 = make_float2(v10, v11);
            }
            *(float2*)(C + (size_t)row0      *EMB + col) = u0;
            *(float2*)(C + (size_t)(row0 + 8)*EMB + col) = u1;
        }
    }
}

__global__ void __launch_bounds__(256) gemm_qkv(
    const float* __restrict__ x,
    const float* __restrict__ Wq, const float* __restrict__ Wk,
    const float* __restrict__ Wv,
    float* __restrict__ q, float* __restrict__ k, float* __restrict__ v)
{
    const float* W = (blockIdx.z == 0) ? Wq : (blockIdx.z == 1) ? Wk : Wv;
    float*       C = (blockIdx.z == 0) ? q  : (blockIdx.z == 1) ? k  : v;
    gemm_body(x, W, nullptr, C, 1);
}
__global__ void __launch_bounds__(256) gemm_out(
    const float* __restrict__ A, const float* __restrict__ W,
    const float* __restrict__ bias, float* __restrict__ C)
{
    gemm_body(A, W, bias, C, 0);
}

#define GEMM_SMEM ((128*36 + 256*36)*2*4)   // 110592 B

// ------------------------------------------------------------------
// Flash attention v2 (causal). grid(16, B*H), 128 threads (4 warps).
// Inputs q,k,v pre-rounded tf32 -> no cvt on loads. cp.async staging for
// Q/K; V transposed via coalesced LDG.32 + conflict-free STS.128.
// Fragment loads via ldmatrix. P relayout via shuffles (no smem P).
// ------------------------------------------------------------------
__global__ void __launch_bounds__(128) attn_kernel(
    const float* __restrict__ Q, const float* __restrict__ K,
    const float* __restrict__ V, float* __restrict__ O)
{
    extern __shared__ uint32_t dyn[];
    uint32_t* Vs = dyn + 192*68;     // 64 x 68 [d][s]
    const uint32_t sbase = (uint32_t)__cvta_generic_to_shared(dyn);
    const uint32_t qsa = sbase;                  // Qs 128 x 68
    const uint32_t ksa = sbase + 128*68*4;       // Ks  64 x 68 [s][d]
    const uint32_t vsa = sbase + 192*68*4;       // Vs  64 x 68 [d][s]

    const int tid  = threadIdx.x;
    const int lane = tid & 31, g = lane >> 2, tg = lane & 3;
    const int wq   = tid >> 5;
    const int qt   = gridDim.x - 1 - blockIdx.x;    // heavy blocks first
    const int b    = blockIdx.y >> 4;
    const int h    = blockIdx.y & 15;
    const int qbase = qt * 128;
    const float cs = 0.125f * 1.44269504088896f;    // 1/sqrt(64)*log2(e)

    const int alr = lane & 15, alk = (lane >> 4) * 4;
    const int blr = (lane & 7) + ((lane >> 4) << 3), blk = ((lane >> 3) & 1) * 4;

    // ---- Q tile -> smem via cp.async (raw, pre-rounded)
    const float* Qg = Q + (size_t)(b*SEQ + qbase)*EMB + h*64;
#pragma unroll
    for (int i = 0; i < 16; i++){
        int id = tid + i*128, r = id >> 4, c4 = id & 15;
        cpa16(qsa + (uint32_t)(r*68 + c4*4)*4, Qg + (size_t)r*EMB + c4*4);
    }
    cpa_commit();

    float mrow[4], lrow[4];
#pragma unroll
    for (int i = 0; i < 4; i++){ mrow[i] = -1e30f; lrow[i] = 0.f; }
    float o[2][8][4];
#pragma unroll
    for (int mi = 0; mi < 2; mi++)
#pragma unroll
        for (int t = 0; t < 8; t++)
#pragma unroll
            for (int j = 0; j < 4; j++) o[mi][t][j] = 0.f;

    const float* Kg = K + (size_t)(b*SEQ)*EMB + h*64;
    const float* Vg = V + (size_t)(b*SEQ)*EMB + h*64;

    const int src0 = (lane & 28) | (tg >> 1);   // shuffle sources for P relayout
    const int src1 = src0 + 2;
    const bool odd = tg & 1;

    const int njt = 2*qt + 2;
    for (int jt = 0; jt < njt; jt++){
        __syncthreads();   // prior compute done: Ks/Vs free
        // K tile -> Ks[s][d] via cp.async
#pragma unroll
        for (int i = 0; i < 8; i++){
            int id = tid + i*128, r = id >> 4, c4 = id & 15;
            cpa16(ksa + (uint32_t)(r*68 + c4*4)*4,
                  Kg + (size_t)(jt*64 + r)*EMB + c4*4);
        }
        cpa_commit();
        // V tile -> Vs[d][s] transposed (coalesced LDG.32, STS.128)
#pragma unroll
        for (int i = 0; i < 8; i++){
            int u  = wq + i*4;
            int s0 = (u & 15) * 4;
            int d  = (u >> 4) * 32 + lane;
            const float* vb = Vg + (size_t)(jt*64 + s0)*EMB + d;
            uint4 pk = make_uint4(__float_as_uint(vb[0]),
                                  __float_as_uint(vb[EMB]),
                                  __float_as_uint(vb[2*EMB]),
                                  __float_as_uint(vb[3*EMB]));
            *(uint4*)&Vs[d*68 + s0] = pk;
        }
        cpa_wait0();
        __syncthreads();

        // ---- S = Q @ K^T : 32 q-rows x 64 keys per warp (ldmatrix frags)
        float sacc[2][8][4];
#pragma unroll
        for (int mi = 0; mi < 2; mi++)
#pragma unroll
            for (int t = 0; t < 8; t++)
#pragma unroll
                for (int j = 0; j < 4; j++) sacc[mi][t][j] = 0.f;
#pragma unroll
        for (int ks = 0; ks < 8; ks++){
            int kk = ks*8;
            uint32_t aq[2][4], bk[4][4];
#pragma unroll
            for (int mi = 0; mi < 2; mi++)
                ldsm4(aq[mi], qsa + (uint32_t)((wq*32 + mi*16 + alr)*68 + kk + alk)*4);
#pragma unroll
            for (int p = 0; p < 4; p++)
                ldsm4(bk[p], ksa + (uint32_t)((p*16 + blr)*68 + kk + blk)*4);
#pragma unroll
            for (int mi = 0; mi < 2; mi++)
#pragma unroll
                for (int p = 0; p < 4; p++){
                    mma8(sacc[mi][2*p],   aq[mi], &bk[p][0]);
                    mma8(sacc[mi][2*p+1], aq[mi], &bk[p][2]);
                }
        }

        // ---- scale + (diagonal-only) causal mask + online softmax
        const bool need_mask = (jt >= 2*qt);
#pragma unroll
        for (int mi = 0; mi < 2; mi++){
            int q0 = qbase + wq*32 + mi*16 + g;
            int q1 = q0 + 8;
            float tm0 = -1e30f, tm1 = -1e30f;
#pragma unroll
            for (int t = 0; t < 8; t++){
                float* s = sacc[mi][t];
                if (need_mask){
                    int jc = jt*64 + t*8 + 2*tg;
                    s[0] = (jc     <= q0) ? s[0]*cs : -1e30f;
                    s[1] = (jc + 1 <= q0) ? s[1]*cs : -1e30f;
                    s[2] = (jc     <= q1) ? s[2]*cs : -1e30f;
                    s[3] = (jc + 1 <= q1) ? s[3]*cs : -1e30f;
                } else {
                    s[0] *= cs; s[1] *= cs; s[2] *= cs; s[3] *= cs;
                }
                tm0 = fmaxf(tm0, fmaxf(s[0], s[1]));
                tm1 = fmaxf(tm1, fmaxf(s[2], s[3]));
            }
            tm0 = fmaxf(tm0, __shfl_xor_sync(0xffffffffu, tm0, 1));
            tm0 = fmaxf(tm0, __shfl_xor_sync(0xffffffffu, tm0, 2));
            tm1 = fmaxf(tm1, __shfl_xor_sync(0xffffffffu, tm1, 1));
            tm1 = fmaxf(tm1, __shfl_xor_sync(0xffffffffu, tm1, 2));
            float mn0 = fmaxf(mrow[mi*2],     tm0);
            float mn1 = fmaxf(mrow[mi*2 + 1], tm1);
            float a0  = ex2f(mrow[mi*2]     - mn0);
            float a1  = ex2f(mrow[mi*2 + 1] - mn1);
            float rs0 = 0.f, rs1 = 0.f;
#pragma unroll
            for (int t = 0; t < 8; t++){
                float* s = sacc[mi][t];
                s[0] = ex2f(s[0] - mn0);
                s[1] = ex2f(s[1] - mn0);
                s[2] = ex2f(s[2] - mn1);
                s[3] = ex2f(s[3] - mn1);
                rs0 += s[0] + s[1];
                rs1 += s[2] + s[3];
            }
            rs0 += __shfl_xor_sync(0xffffffffu, rs0, 1);
            rs0 += __shfl_xor_sync(0xffffffffu, rs0, 2);
            rs1 += __shfl_xor_sync(0xffffffffu, rs1, 1);
            rs1 += __shfl_xor_sync(0xffffffffu, rs1, 2);
            lrow[mi*2]     = lrow[mi*2]*a0     + rs0;
            lrow[mi*2 + 1] = lrow[mi*2 + 1]*a1 + rs1;
            mrow[mi*2]     = mn0;
            mrow[mi*2 + 1] = mn1;
#pragma unroll
            for (int t = 0; t < 8; t++){
                o[mi][t][0] *= a0; o[mi][t][1] *= a0;
                o[mi][t][2] *= a1; o[mi][t][3] *= a1;
            }
        }

        // ---- O += P @ V : A-frags from sacc via shuffles, B via ldmatrix
#pragma unroll
        for (int ks = 0; ks < 8; ks++){
            int kk = ks*8;
            uint32_t bv[4][4];
#pragma unroll
            for (int p = 0; p < 4; p++)
                ldsm4(bv[p], vsa + (uint32_t)((p*16 + blr)*68 + kk + blk)*4);
#pragma unroll
            for (int mi = 0; mi < 2; mi++){
                float x0 = sacc[mi][ks][0], x1 = sacc[mi][ks][1];
                float x2 = sacc[mi][ks][2], x3 = sacc[mi][ks][3];
                float y0 = __shfl_sync(0xffffffffu, x0, src0);
                float y1 = __shfl_sync(0xffffffffu, x1, src0);
                float y2 = __shfl_sync(0xffffffffu, x2, src0);
                float y3 = __shfl_sync(0xffffffffu, x3, src0);
                float z0 = __shfl_sync(0xffffffffu, x0, src1);
                float z1 = __shfl_sync(0xffffffffu, x1, src1);
                float z2 = __shfl_sync(0xffffffffu, x2, src1);
                float z3 = __shfl_sync(0xffffffffu, x3, src1);
                uint32_t av[4];
                av[0] = f2tf(odd ? y1 : y0);
                av[1] = f2tf(odd ? y3 : y2);
                av[2] = f2tf(odd ? z1 : z0);
                av[3] = f2tf(odd ? z3 : z2);
#pragma unroll
                for (int p = 0; p < 4; p++){
                    mma8(o[mi][2*p],   av, &bv[p][0]);
                    mma8(o[mi][2*p+1], av, &bv[p][2]);
                }
            }
        }
    }

    // ---- epilogue: normalize, pre-round to tf32 (feeds final GEMM), store
#pragma unroll
    for (int mi = 0; mi < 2; mi++){
        float i0 = 1.f / lrow[mi*2];
        float i1 = 1.f / lrow[mi*2 + 1];
        size_t q0 = (size_t)(b*SEQ + qbase + wq*32 + mi*16 + g);
#pragma unroll
        for (int t = 0; t < 8; t++){
            int col = h*64 + t*8 + 2*tg;
            float2 v0 = make_float2(__uint_as_float(f2tf(o[mi][t][0]*i0)),
                                    __uint_as_float(f2tf(o[mi][t][1]*i0)));
            float2 v1 = make_float2(__uint_as_float(f2tf(o[mi][t][2]*i1)),
                                    __uint_as_float(f2tf(o[mi][t][3]*i1)));
            *(float2*)(O + q0*EMB + col)       = v0;
            *(float2*)(O + (q0 + 8)*EMB + col) = v1;
        }
    }
}

#define ATTN_SMEM (256*68*4)

// ------------------------------------------------------------------
extern "C" void kernel_launch(void* const* d_in, const int* in_sizes, int n_in,
                              void* d_out, int out_size)
{
    const float* x  = (const float*)d_in[0];
    const float* Wq = (const float*)d_in[1];
    const float* Wk = (const float*)d_in[2];
    const float* Wv = (const float*)d_in[3];
    const float* Wo = (const float*)d_in[4];
    const float* bo = (const float*)d_in[5];
    float* out = (float*)d_out;

    float *q, *k, *v, *ao, *xc, *wq, *wk, *wv, *wo;
    cudaGetSymbolAddress((void**)&q,  g_q);
    cudaGetSymbolAddress((void**)&k,  g_k);
    cudaGetSymbolAddress((void**)&v,  g_v);
    cudaGetSymbolAddress((void**)&ao, g_ao);
    cudaGetSymbolAddress((void**)&xc, g_xc);
    cudaGetSymbolAddress((void**)&wq, g_wq);
    cudaGetSymbolAddress((void**)&wk, g_wk);
    cudaGetSymbolAddress((void**)&wv, g_wv);
    cudaGetSymbolAddress((void**)&wo, g_wo);

    cudaFuncSetAttribute(gemm_qkv,
                         cudaFuncAttributeMaxDynamicSharedMemorySize, GEMM_SMEM);
    cudaFuncSetAttribute(gemm_out,
                         cudaFuncAttributeMaxDynamicSharedMemorySize, GEMM_SMEM);
    cudaFuncSetAttribute(attn_kernel,
                         cudaFuncAttributeMaxDynamicSharedMemorySize, ATTN_SMEM);

    // pre-round inputs to tf32 (rna) — numerically identical to in-GEMM cvt
    const int nx4 = MR*EMB/4, nw4 = EMB*EMB/4;
    cvt_tf32_k<<<(nx4+255)/256, 256>>>((const float4*)x,  (float4*)xc, nx4);
    cvt_tf32_k<<<(nw4+255)/256, 256>>>((const float4*)Wq, (float4*)wq, nw4);
    cvt_tf32_k<<<(nw4+255)/256, 256>>>((const float4*)Wk, (float4*)wk, nw4);
    cvt_tf32_k<<<(nw4+255)/256, 256>>>((const float4*)Wv, (float4*)wv, nw4);
    cvt_tf32_k<<<(nw4+255)/256, 256>>>((const float4*)Wo, (float4*)wo, nw4);

    dim3 gq(EMB/256, MR/128, 3);          // 4 x 64 x 3
    gemm_qkv<<<gq, 256, GEMM_SMEM>>>(xc, wq, wk, wv, q, k, v);

    dim3 ga(SEQ/128, NB*NH);              // 16 x 64
    attn_kernel<<<ga, 128, ATTN_SMEM>>>(q, k, v, ao);

    dim3 go(EMB/256, MR/128);             // 4 x 64
    gemm_out<<<go, 256, GEMM_SMEM>>>(ao, wo, bo, out);
}

// round 8
// speedup vs baseline: 2.2777x; 1.5142x over previous
#include <cuda_runtime.h>
#include <cuda_fp16.h>
#include <cstdint>
#include <cstddef>

#define EMB 1024
#define SEQ 2048
#define NB  4
#define NH  16
#define MR  (NB*SEQ)   // 8192 rows

// static device scratch (allocation-guard safe) — fp16 activations/weights
__device__ __half g_q [(size_t)MR*EMB];
__device__ __half g_k [(size_t)MR*EMB];
__device__ __half g_v [(size_t)MR*EMB];
__device__ __half g_ao[(size_t)MR*EMB];
__device__ __half g_xc[(size_t)MR*EMB];
__device__ __half g_wq[(size_t)EMB*EMB];
__device__ __half g_wk[(size_t)EMB*EMB];
__device__ __half g_wv[(size_t)EMB*EMB];
__device__ __half g_wo[(size_t)EMB*EMB];

__device__ __forceinline__ float ex2f(float x){
    float y; asm("ex2.approx.ftz.f32 %0, %1;" : "=f"(y) : "f"(x)); return y;
}
// D += A*B : m16n8k16 fp16 in / fp32 accum.
// A frag (16x16): a0=(g, 2tg..+1) a1=(g+8, 2tg..) a2=(g, 2tg+8..) a3=(g+8, 2tg+8..)
// B frag (16x8):  b0=(k=2tg..+1, n=g) b1=(k=2tg+8.., n=g)
// C frag: c0=(g,2tg) c1=(g,2tg+1) c2=(g+8,2tg) c3=(g+8,2tg+1)
__device__ __forceinline__ void mma16(float* d, const uint32_t* a,
                                      uint32_t b0, uint32_t b1){
    asm volatile(
      "mma.sync.aligned.m16n8k16.row.col.f32.f16.f16.f32 "
      "{%0,%1,%2,%3}, {%4,%5,%6,%7}, {%8,%9}, {%0,%1,%2,%3};\n"
      : "+f"(d[0]), "+f"(d[1]), "+f"(d[2]), "+f"(d[3])
      : "r"(a[0]), "r"(a[1]), "r"(a[2]), "r"(a[3]), "r"(b0), "r"(b1));
}
__device__ __forceinline__ void ldsm4(uint32_t* r, uint32_t saddr){
    asm volatile("ldmatrix.sync.aligned.m8n8.x4.shared.b16 {%0,%1,%2,%3}, [%4];"
        : "=r"(r[0]), "=r"(r[1]), "=r"(r[2]), "=r"(r[3]) : "r"(saddr));
}
__device__ __forceinline__ void cpa16(uint32_t saddr, const void* g){
    asm volatile("cp.async.ca.shared.global [%0], [%1], 16;" :: "r"(saddr), "l"(g));
}
__device__ __forceinline__ void cpa_commit(){ asm volatile("cp.async.commit_group;"); }
__device__ __forceinline__ void cpa_wait0(){ asm volatile("cp.async.wait_group 0;"); }
__device__ __forceinline__ void cpa_wait1(){ asm volatile("cp.async.wait_group 1;"); }
__device__ __forceinline__ uint32_t ph2(float lo, float hi){
    __half2 t = __floats2half2_rn(lo, hi);
    return *(uint32_t*)&t;
}

// ------------------------------------------------------------------
// elementwise fp32 -> fp16 pre-round
// ------------------------------------------------------------------
__global__ void __launch_bounds__(256) cvt_f2h(
    const float4* __restrict__ src, uint2* __restrict__ dst, int n4)
{
    int i = blockIdx.x*256 + threadIdx.x;
    if (i < n4){
        float4 v = src[i];
        uint2 o;
        o.x = ph2(v.x, v.y);
        o.y = ph2(v.z, v.w);
        dst[i] = o;
    }
}

// ------------------------------------------------------------------
// fp16 GEMM: C[M,N] = A[M,K] @ W[N,K]^T (+bias). M=8192, N=K=1024.
// Block 128(m) x 256(n), BK=64 halves, 256 thr, warps 2(m)x4(n) -> 64x64.
// cp.async double-buffered; row stride 72 halves (144B: 16B multiple, rows
// 0..7 -> distinct 16B bank groups => conflict-free ldmatrix).
// ------------------------------------------------------------------
#define RS   144                              // row stride bytes
#define GA_B (128*RS)                         // 18432
#define GB_B (256*RS)                         // 36864
#define GSTG (GA_B + GB_B)                    // 55296
#define GEMM_SMEM (2*GSTG)                    // 110592

__device__ __forceinline__ void gemm_body(
    const __half* __restrict__ A, const __half* __restrict__ W,
    const float* __restrict__ bias, void* __restrict__ C, int out_half)
{
    extern __shared__ uint32_t sh[];
    const uint32_t sbase = (uint32_t)__cvta_generic_to_shared(sh);

    const int tid  = threadIdx.x;
    const int lane = tid & 31, g = lane >> 2, tg = lane & 3;
    const int wid  = tid >> 5;
    const int wm   = (wid & 1) * 64;
    const int wn   = (wid >> 1) * 64;
    const int bm   = blockIdx.y * 128;
    const int bn   = blockIdx.x * 256;

    const int alr = lane & 15;                // ldsm row within 16
    const int alk = (lane >> 4) * 16;         // ldsm 16B col select

    const __half* Ag = A + (size_t)bm*EMB;
    const __half* Wg = W + (size_t)bn*EMB;

    float acc[4][8][4];
#pragma unroll
    for (int mi = 0; mi < 4; mi++)
#pragma unroll
        for (int t = 0; t < 8; t++)
#pragma unroll
            for (int j = 0; j < 4; j++) acc[mi][t][j] = 0.f;

    auto stage = [&](int kt, int s){
        const uint32_t sa = sbase + (uint32_t)s*GSTG;
        const uint32_t sb = sa + GA_B;
#pragma unroll
        for (int i = 0; i < 4; i++){           // A: 128 rows x 8 chunks
            int id = tid + i*256, r = id >> 3, c = id & 7;
            cpa16(sa + r*RS + c*16, Ag + (size_t)r*EMB + kt*64 + c*8);
        }
#pragma unroll
        for (int i = 0; i < 8; i++){           // B: 256 rows x 8 chunks
            int id = tid + i*256, r = id >> 3, c = id & 7;
            cpa16(sb + r*RS + c*16, Wg + (size_t)r*EMB + kt*64 + c*8);
        }
        cpa_commit();
    };

    stage(0, 0);
    stage(1, 1);

    const int nk = EMB/64;   // 16
    for (int kt = 0; kt < nk; kt++){
        const int s = kt & 1;
        if (kt + 1 < nk) cpa_wait1(); else cpa_wait0();
        __syncthreads();
        const uint32_t sa = sbase + (uint32_t)s*GSTG;
        const uint32_t sb = sa + GA_B;
#pragma unroll
        for (int kk = 0; kk < 4; kk++){        // 4 x k16
            uint32_t af[4][4], bf[4][4];
#pragma unroll
            for (int mi = 0; mi < 4; mi++)
                ldsm4(af[mi], sa + (wm + mi*16 + alr)*RS + kk*32 + alk);
#pragma unroll
            for (int p = 0; p < 4; p++)
                ldsm4(bf[p], sb + (wn + p*16 + alr)*RS + kk*32 + alk);
#pragma unroll
            for (int mi = 0; mi < 4; mi++)
#pragma unroll
                for (int p = 0; p < 4; p++){
                    mma16(acc[mi][2*p],   af[mi], bf[p][0], bf[p][2]);
                    mma16(acc[mi][2*p+1], af[mi], bf[p][1], bf[p][3]);
                }
        }
        __syncthreads();
        if (kt + 2 < nk) stage(kt + 2, s);
    }

    // epilogue
#pragma unroll
    for (int mi = 0; mi < 4; mi++){
#pragma unroll
        for (int t = 0; t < 8; t++){
            int col  = bn + wn + t*8 + 2*tg;
            int row0 = bm + wm + mi*16 + g;
            if (out_half){
                __half2 h0 = __floats2half2_rn(acc[mi][t][0], acc[mi][t][1]);
                __half2 h1 = __floats2half2_rn(acc[mi][t][2], acc[mi][t][3]);
                *(__half2*)((__half*)C + (size_t)row0      *EMB + col) = h0;
                *(__half2*)((__half*)C + (size_t)(row0 + 8)*EMB + col) = h1;
            } else {
                float b0 = bias ? bias[col]   : 0.f;
                float b1 = bias ? bias[col+1] : 0.f;
                float2 v0 = make_float2(acc[mi][t][0] + b0, acc[mi][t][1] + b1);
                float2 v1 = make_float2(acc[mi][t][2] + b0, acc[mi][t][3] + b1);
                *(float2*)((float*)C + (size_t)row0      *EMB + col) = v0;
                *(float2*)((float*)C + (size_t)(row0 + 8)*EMB + col) = v1;
            }
        }
    }
}

__global__ void __launch_bounds__(256) gemm_qkv(
    const __half* __restrict__ x,
    const __half* __restrict__ Wq, const __half* __restrict__ Wk,
    const __half* __restrict__ Wv,
    __half* __restrict__ q, __half* __restrict__ k, __half* __restrict__ v)
{
    const __half* W = (blockIdx.z == 0) ? Wq : (blockIdx.z == 1) ? Wk : Wv;
    __half*       C = (blockIdx.z == 0) ? q  : (blockIdx.z == 1) ? k  : v;
    gemm_body(x, W, nullptr, C, 1);
}
__global__ void __launch_bounds__(256) gemm_out(
    const __half* __restrict__ A, const __half* __restrict__ W,
    const float* __restrict__ bias, float* __restrict__ C)
{
    gemm_body(A, W, bias, C, 0);
}

// ------------------------------------------------------------------
// Flash attention v2 (causal), fp16 operands / fp32 softmax+accum.
// grid(16, B*H), 128 threads. q-tile 128/block, warp 32 q rows.
// d=64 -> 4 k16 steps. PV A-frags packed directly from S C-frags
// (f16 layout identity — no shuffles). Smem rows stride 72 halves.
// ------------------------------------------------------------------
#define QS_B (128*RS)      // 18432
#define KS_B (64*RS)       //  9216
#define ATTN_SMEM (QS_B + 2*KS_B)   // 36864

__global__ void __launch_bounds__(128) attn_kernel(
    const __half* __restrict__ Q, const __half* __restrict__ K,
    const __half* __restrict__ V, __half* __restrict__ O)
{
    extern __shared__ uint32_t dyn[];
    __half* Vh = (__half*)dyn + (QS_B + KS_B)/2;   // generic ptr for V stores
    const uint32_t sbase = (uint32_t)__cvta_generic_to_shared(dyn);
    const uint32_t qsa = sbase;
    const uint32_t ksa = sbase + QS_B;
    const uint32_t vsa = sbase + QS_B + KS_B;

    const int tid  = threadIdx.x;
    const int lane = tid & 31, g = lane >> 2, tg = lane & 3;
    const int wq   = tid >> 5;
    const int qt   = gridDim.x - 1 - blockIdx.x;    // heavy blocks first
    const int b    = blockIdx.y >> 4;
    const int h    = blockIdx.y & 15;
    const int qbase = qt * 128;
    const float cs = 0.125f * 1.44269504088896f;    // 1/sqrt(64)*log2(e)

    const int alr = lane & 15, alk = (lane >> 4) * 16;

    // Q tile -> smem (cp.async): 128 rows x 8 x 16B
    const __half* Qg = Q + (size_t)(b*SEQ + qbase)*EMB + h*64;
#pragma unroll
    for (int i = 0; i < 8; i++){
        int id = tid + i*128, r = id >> 3, c = id & 7;
        cpa16(qsa + r*RS + c*16, Qg + (size_t)r*EMB + c*8);
    }
    cpa_commit();

    float mrow[4], lrow[4];
#pragma unroll
    for (int i = 0; i < 4; i++){ mrow[i] = -1e30f; lrow[i] = 0.f; }
    float o[2][8][4];
#pragma unroll
    for (int mi = 0; mi < 2; mi++)
#pragma unroll
        for (int t = 0; t < 8; t++)
#pragma unroll
            for (int j = 0; j < 4; j++) o[mi][t][j] = 0.f;

    const __half* Kg = K + (size_t)(b*SEQ)*EMB + h*64;
    const __half* Vg = V + (size_t)(b*SEQ)*EMB + h*64;

    const int njt = 2*qt + 2;
    for (int jt = 0; jt < njt; jt++){
        __syncthreads();   // prior compute done: Ks/Vs free
        // K tile -> Ks[s][d] (64 rows x 8 x 16B)
#pragma unroll
        for (int i = 0; i < 4; i++){
            int id = tid + i*128, r = id >> 3, c = id & 7;
            cpa16(ksa + r*RS + c*16, Kg + (size_t)(jt*64 + r)*EMB + c*8);
        }
        cpa_commit();
        // V tile -> Vs[d][s] transposed
#pragma unroll
        for (int i = 0; i < 8; i++){
            int u  = wq + i*4;              // 0..31 unique
            int s0 = (u & 15) * 4;
            int d  = (u >> 4) * 32 + lane;
            const __half* vb = Vg + (size_t)(jt*64 + s0)*EMB + d;
            __half2 p0 = __halves2half2(vb[0],      vb[EMB]);
            __half2 p1 = __halves2half2(vb[2*EMB],  vb[3*EMB]);
            uint2 u2; u2.x = *(uint32_t*)&p0; u2.y = *(uint32_t*)&p1;
            *(uint2*)(Vh + (size_t)d*(RS/2) + s0) = u2;
        }
        cpa_wait0();
        __syncthreads();

        // ---- S = Q @ K^T : 32 q-rows x 64 keys per warp
        float sacc[2][8][4];
#pragma unroll
        for (int mi = 0; mi < 2; mi++)
#pragma unroll
            for (int t = 0; t < 8; t++)
#pragma unroll
                for (int j = 0; j < 4; j++) sacc[mi][t][j] = 0.f;
#pragma unroll
        for (int ks = 0; ks < 4; ks++){        // 4 x k16 over d
            uint32_t aq[2][4], bk[4][4];
#pragma unroll
            for (int mi = 0; mi < 2; mi++)
                ldsm4(aq[mi], qsa + (wq*32 + mi*16 + alr)*RS + ks*32 + alk);
#pragma unroll
            for (int p = 0; p < 4; p++)
                ldsm4(bk[p], ksa + (p*16 + alr)*RS + ks*32 + alk);
#pragma unroll
            for (int mi = 0; mi < 2; mi++)
#pragma unroll
                for (int p = 0; p < 4; p++){
                    mma16(sacc[mi][2*p],   aq[mi], bk[p][0], bk[p][2]);
                    mma16(sacc[mi][2*p+1], aq[mi], bk[p][1], bk[p][3]);
                }
        }

        // ---- scale + (diagonal-only) causal mask + online softmax
        const bool need_mask = (jt >= 2*qt);
#pragma unroll
        for (int mi = 0; mi < 2; mi++){
            int q0 = qbase + wq*32 + mi*16 + g;
            int q1 = q0 + 8;
            float tm0 = -1e30f, tm1 = -1e30f;
#pragma unroll
            for (int t = 0; t < 8; t++){
                float* s = sacc[mi][t];
                if (need_mask){
                    int jc = jt*64 + t*8 + 2*tg;
                    s[0] = (jc     <= q0) ? s[0]*cs : -1e30f;
                    s[1] = (jc + 1 <= q0) ? s[1]*cs : -1e30f;
                    s[2] = (jc     <= q1) ? s[2]*cs : -1e30f;
                    s[3] = (jc + 1 <= q1) ? s[3]*cs : -1e30f;
                } else {
                    s[0] *= cs; s[1] *= cs; s[2] *= cs; s[3] *= cs;
                }
                tm0 = fmaxf(tm0, fmaxf(s[0], s[1]));
                tm1 = fmaxf(tm1, fmaxf(s[2], s[3]));
            }
            tm0 = fmaxf(tm0, __shfl_xor_sync(0xffffffffu, tm0, 1));
            tm0 = fmaxf(tm0, __shfl_xor_sync(0xffffffffu, tm0, 2));
            tm1 = fmaxf(tm1, __shfl_xor_sync(0xffffffffu, tm1, 1));
            tm1 = fmaxf(tm1, __shfl_xor_sync(0xffffffffu, tm1, 2));
            float mn0 = fmaxf(mrow[mi*2],     tm0);
            float mn1 = fmaxf(mrow[mi*2 + 1], tm1);
            float a0  = ex2f(mrow[mi*2]     - mn0);
            float a1  = ex2f(mrow[mi*2 + 1] - mn1);
            float rs0 = 0.f, rs1 = 0.f;
#pragma unroll
            for (int t = 0; t < 8; t++){
                float* s = sacc[mi][t];
                s[0] = ex2f(s[0] - mn0);
                s[1] = ex2f(s[1] - mn0);
                s[2] = ex2f(s[2] - mn1);
                s[3] = ex2f(s[3] - mn1);
                rs0 += s[0] + s[1];
                rs1 += s[2] + s[3];
            }
            rs0 += __shfl_xor_sync(0xffffffffu, rs0, 1);
            rs0 += __shfl_xor_sync(0xffffffffu, rs0, 2);
            rs1 += __shfl_xor_sync(0xffffffffu, rs1, 1);
            rs1 += __shfl_xor_sync(0xffffffffu, rs1, 2);
            lrow[mi*2]     = lrow[mi*2]*a0     + rs0;
            lrow[mi*2 + 1] = lrow[mi*2 + 1]*a1 + rs1;
            mrow[mi*2]     = mn0;
            mrow[mi*2 + 1] = mn1;
#pragma unroll
            for (int t = 0; t < 8; t++){
                o[mi][t][0] *= a0; o[mi][t][1] *= a0;
                o[mi][t][2] *= a1; o[mi][t][3] *= a1;
            }
        }

        // ---- O += P @ V : A-frags packed straight from S C-frags (f16)
#pragma unroll
        for (int ks = 0; ks < 4; ks++){        // 4 x k16 over keys
            uint32_t bv[4][4];
#pragma unroll
            for (int p = 0; p < 4; p++)
                ldsm4(bv[p], vsa + (p*16 + alr)*RS + ks*32 + alk);
#pragma unroll
            for (int mi = 0; mi < 2; mi++){
                uint32_t av[4];
                av[0] = ph2(sacc[mi][2*ks][0],   sacc[mi][2*ks][1]);
                av[1] = ph2(sacc[mi][2*ks][2],   sacc[mi][2*ks][3]);
                av[2] = ph2(sacc[mi][2*ks+1][0], sacc[mi][2*ks+1][1]);
                av[3] = ph2(sacc[mi][2*ks+1][2], sacc[mi][2*ks+1][3]);
#pragma unroll
                for (int p = 0; p < 4; p++){
                    mma16(o[mi][2*p],   av, bv[p][0], bv[p][2]);
                    mma16(o[mi][2*p+1], av, bv[p][1], bv[p][3]);
                }
            }
        }
    }

    // ---- epilogue: normalize, store half (feeds final GEMM)
#pragma unroll
    for (int mi = 0; mi < 2; mi++){
        float i0 = 1.f / lrow[mi*2];
        float i1 = 1.f / lrow[mi*2 + 1];
        size_t q0 = (size_t)(b*SEQ + qbase + wq*32 + mi*16 + g);
#pragma unroll
        for (int t = 0; t < 8; t++){
            int col = h*64 + t*8 + 2*tg;
            __half2 h0 = __floats2half2_rn(o[mi][t][0]*i0, o[mi][t][1]*i0);
            __half2 h1 = __floats2half2_rn(o[mi][t][2]*i1, o[mi][t][3]*i1);
            *(__half2*)(O + q0*EMB + col)       = h0;
            *(__half2*)(O + (q0 + 8)*EMB + col) = h1;
        }
    }
}

// ------------------------------------------------------------------
extern "C" void kernel_launch(void* const* d_in, const int* in_sizes, int n_in,
                              void* d_out, int out_size)
{
    const float* x  = (const float*)d_in[0];
    const float* Wq = (const float*)d_in[1];
    const float* Wk = (const float*)d_in[2];
    const float* Wv = (const float*)d_in[3];
    const float* Wo = (const float*)d_in[4];
    const float* bo = (const float*)d_in[5];
    float* out = (float*)d_out;

    __half *q, *k, *v, *ao, *xc, *wq, *wk, *wv, *wo;
    cudaGetSymbolAddress((void**)&q,  g_q);
    cudaGetSymbolAddress((void**)&k,  g_k);
    cudaGetSymbolAddress((void**)&v,  g_v);
    cudaGetSymbolAddress((void**)&ao, g_ao);
    cudaGetSymbolAddress((void**)&xc, g_xc);
    cudaGetSymbolAddress((void**)&wq, g_wq);
    cudaGetSymbolAddress((void**)&wk, g_wk);
    cudaGetSymbolAddress((void**)&wv, g_wv);
    cudaGetSymbolAddress((void**)&wo, g_wo);

    cudaFuncSetAttribute(gemm_qkv,
                         cudaFuncAttributeMaxDynamicSharedMemorySize, GEMM_SMEM);
    cudaFuncSetAttribute(gemm_out,
                         cudaFuncAttributeMaxDynamicSharedMemorySize, GEMM_SMEM);

    // pre-round inputs to fp16
    const int nx4 = MR*EMB/4, nw4 = EMB*EMB/4;
    cvt_f2h<<<(nx4+255)/256, 256>>>((const float4*)x,  (uint2*)xc, nx4);
    cvt_f2h<<<(nw4+255)/256, 256>>>((const float4*)Wq, (uint2*)wq, nw4);
    cvt_f2h<<<(nw4+255)/256, 256>>>((const float4*)Wk, (uint2*)wk, nw4);
    cvt_f2h<<<(nw4+255)/256, 256>>>((const float4*)Wv, (uint2*)wv, nw4);
    cvt_f2h<<<(nw4+255)/256, 256>>>((const float4*)Wo, (uint2*)wo, nw4);

    dim3 gq(EMB/256, MR/128, 3);          // 4 x 64 x 3
    gemm_qkv<<<gq, 256, GEMM_SMEM>>>(xc, wq, wk, wv, q, k, v);

    dim3 ga(SEQ/128, NB*NH);              // 16 x 64
    attn_kernel<<<ga, 128, ATTN_SMEM>>>(q, k, v, ao);

    dim3 go(EMB/256, MR/128);             // 4 x 64
    gemm_out<<<go, 256, GEMM_SMEM>>>(ao, wo, bo, out);
}

// round 10
// speedup vs baseline: 2.5375x; 1.1140x over previous
#include <cuda_runtime.h>
#include <cuda_fp16.h>
#include <cstdint>
#include <cstddef>

#define EMB 1024
#define SEQ 2048
#define NB  4
#define NH  16
#define MR  (NB*SEQ)   // 8192 rows

// static device scratch (allocation-guard safe) — fp16 activations/weights
__device__ __half g_q [(size_t)MR*EMB];
__device__ __half g_k [(size_t)MR*EMB];
__device__ __half g_v [(size_t)MR*EMB];
__device__ __half g_ao[(size_t)MR*EMB];
__device__ __half g_xc[(size_t)MR*EMB];
__device__ __half g_wq[(size_t)EMB*EMB];
__device__ __half g_wk[(size_t)EMB*EMB];
__device__ __half g_wv[(size_t)EMB*EMB];
__device__ __half g_wo[(size_t)EMB*EMB];

__device__ __forceinline__ float ex2f(float x){
    float y; asm("ex2.approx.ftz.f32 %0, %1;" : "=f"(y) : "f"(x)); return y;
}
// D += A*B : m16n8k16 fp16 in / fp32 accum.
// A frag: a0=(g,2tg..) a1=(g+8,2tg..) a2=(g,2tg+8..) a3=(g+8,2tg+8..)
// B frag: b0=(k=2tg..,n=g) b1=(k=2tg+8..,n=g)
// C frag: c0=(g,2tg) c1=(g,2tg+1) c2=(g+8,2tg) c3=(g+8,2tg+1)
__device__ __forceinline__ void mma16(float* d, const uint32_t* a,
                                      uint32_t b0, uint32_t b1){
    asm volatile(
      "mma.sync.aligned.m16n8k16.row.col.f32.f16.f16.f32 "
      "{%0,%1,%2,%3}, {%4,%5,%6,%7}, {%8,%9}, {%0,%1,%2,%3};\n"
      : "+f"(d[0]), "+f"(d[1]), "+f"(d[2]), "+f"(d[3])
      : "r"(a[0]), "r"(a[1]), "r"(a[2]), "r"(a[3]), "r"(b0), "r"(b1));
}
__device__ __forceinline__ void ldsm4(uint32_t* r, uint32_t saddr){
    asm volatile("ldmatrix.sync.aligned.m8n8.x4.shared.b16 {%0,%1,%2,%3}, [%4];"
        : "=r"(r[0]), "=r"(r[1]), "=r"(r[2]), "=r"(r[3]) : "r"(saddr));
}
__device__ __forceinline__ void ldsm4t(uint32_t* r, uint32_t saddr){
    asm volatile("ldmatrix.sync.aligned.m8n8.x4.trans.shared.b16 {%0,%1,%2,%3}, [%4];"
        : "=r"(r[0]), "=r"(r[1]), "=r"(r[2]), "=r"(r[3]) : "r"(saddr));
}
__device__ __forceinline__ void cpa16(uint32_t saddr, const void* g){
    asm volatile("cp.async.ca.shared.global [%0], [%1], 16;" :: "r"(saddr), "l"(g));
}
__device__ __forceinline__ void cpa_commit(){ asm volatile("cp.async.commit_group;"); }
__device__ __forceinline__ void cpa_wait0(){ asm volatile("cp.async.wait_group 0;"); }
__device__ __forceinline__ void cpa_wait1(){ asm volatile("cp.async.wait_group 1;"); }
__device__ __forceinline__ uint32_t ph2(float lo, float hi){
    __half2 t = __floats2half2_rn(lo, hi);
    return *(uint32_t*)&t;
}

// ------------------------------------------------------------------
// fp32 -> fp16 pre-round: x (single) and 4 weights (grid.y)
// ------------------------------------------------------------------
__global__ void __launch_bounds__(256) cvt_f2h(
    const float4* __restrict__ src, uint2* __restrict__ dst, int n4)
{
    int i = blockIdx.x*256 + threadIdx.x;
    if (i < n4){
        float4 v = src[i];
        uint2 o; o.x = ph2(v.x, v.y); o.y = ph2(v.z, v.w);
        dst[i] = o;
    }
}
__global__ void __launch_bounds__(256) cvt_f2h4(
    const float4* __restrict__ s0, const float4* __restrict__ s1,
    const float4* __restrict__ s2, const float4* __restrict__ s3,
    uint2* __restrict__ d0, uint2* __restrict__ d1,
    uint2* __restrict__ d2, uint2* __restrict__ d3, int n4)
{
    const float4* s = (blockIdx.y==0)?s0:(blockIdx.y==1)?s1:(blockIdx.y==2)?s2:s3;
    uint2*        d = (blockIdx.y==0)?d0:(blockIdx.y==1)?d1:(blockIdx.y==2)?d2:d3;
    int i = blockIdx.x*256 + threadIdx.x;
    if (i < n4){
        float4 v = s[i];
        uint2 o; o.x = ph2(v.x, v.y); o.y = ph2(v.z, v.w);
        d[i] = o;
    }
}

// ------------------------------------------------------------------
// fp16 GEMM (R8-proven): C[M,N] = A[M,K] @ W[N,K]^T (+bias).
// Block 128(m) x 256(n), BK=64 halves, 256 thr, warps 2(m)x4(n) -> 64x64.
// cp.async double-buffered; row stride 144B (9x16B): rows r..r+7 hit
// distinct 16B bank groups => conflict-free ldmatrix.
// ------------------------------------------------------------------
#define RS   144                              // row stride bytes
#define GA_B (128*RS)                         // 18432
#define GB_B (256*RS)                         // 36864
#define GSTG (GA_B + GB_B)                    // 55296
#define GEMM_SMEM (2*GSTG)                    // 110592

__device__ __forceinline__ void gemm_body(
    const __half* __restrict__ A, const __half* __restrict__ W,
    const float* __restrict__ bias, void* __restrict__ C, int out_half)
{
    extern __shared__ uint32_t sh[];
    const uint32_t sbase = (uint32_t)__cvta_generic_to_shared(sh);

    const int tid  = threadIdx.x;
    const int lane = tid & 31, g = lane >> 2, tg = lane & 3;
    const int wid  = tid >> 5;
    const int wm   = (wid & 1) * 64;
    const int wn   = (wid >> 1) * 64;
    const int bm   = blockIdx.y * 128;
    const int bn   = blockIdx.x * 256;

    const int alr = lane & 15;                // ldsm row within 16
    const int alk = (lane >> 4) * 16;         // ldsm 16B col select

    const __half* Ag = A + (size_t)bm*EMB;
    const __half* Wg = W + (size_t)bn*EMB;

    float acc[4][8][4];
#pragma unroll
    for (int mi = 0; mi < 4; mi++)
#pragma unroll
        for (int t = 0; t < 8; t++)
#pragma unroll
            for (int j = 0; j < 4; j++) acc[mi][t][j] = 0.f;

    auto stage = [&](int kt, int s){
        const uint32_t sa = sbase + (uint32_t)s*GSTG;
        const uint32_t sb = sa + GA_B;
#pragma unroll
        for (int i = 0; i < 4; i++){           // A: 128 rows x 8 chunks
            int id = tid + i*256, r = id >> 3, c = id & 7;
            cpa16(sa + r*RS + c*16, Ag + (size_t)r*EMB + kt*64 + c*8);
        }
#pragma unroll
        for (int i = 0; i < 8; i++){           // B: 256 rows x 8 chunks
            int id = tid + i*256, r = id >> 3, c = id & 7;
            cpa16(sb + r*RS + c*16, Wg + (size_t)r*EMB + kt*64 + c*8);
        }
        cpa_commit();
    };

    stage(0, 0);
    stage(1, 1);

    const int nk = EMB/64;   // 16
    for (int kt = 0; kt < nk; kt++){
        const int s = kt & 1;
        if (kt + 1 < nk) cpa_wait1(); else cpa_wait0();
        __syncthreads();
        const uint32_t sa = sbase + (uint32_t)s*GSTG;
        const uint32_t sb = sa + GA_B;
#pragma unroll
        for (int kk = 0; kk < 4; kk++){        // 4 x k16
            uint32_t af[4][4], bf[4][4];
#pragma unroll
            for (int mi = 0; mi < 4; mi++)
                ldsm4(af[mi], sa + (wm + mi*16 + alr)*RS + kk*32 + alk);
#pragma unroll
            for (int p = 0; p < 4; p++)
                ldsm4(bf[p], sb + (wn + p*16 + alr)*RS + kk*32 + alk);
#pragma unroll
            for (int mi = 0; mi < 4; mi++)
#pragma unroll
                for (int p = 0; p < 4; p++){
                    mma16(acc[mi][2*p],   af[mi], bf[p][0], bf[p][2]);
                    mma16(acc[mi][2*p+1], af[mi], bf[p][1], bf[p][3]);
                }
        }
        __syncthreads();
        if (kt + 2 < nk) stage(kt + 2, s);
    }

    // epilogue
#pragma unroll
    for (int mi = 0; mi < 4; mi++){
#pragma unroll
        for (int t = 0; t < 8; t++){
            int col  = bn + wn + t*8 + 2*tg;
            int row0 = bm + wm + mi*16 + g;
            if (out_half){
                __half2 h0 = __floats2half2_rn(acc[mi][t][0], acc[mi][t][1]);
                __half2 h1 = __floats2half2_rn(acc[mi][t][2], acc[mi][t][3]);
                *(__half2*)((__half*)C + (size_t)row0      *EMB + col) = h0;
                *(__half2*)((__half*)C + (size_t)(row0 + 8)*EMB + col) = h1;
            } else {
                float b0 = bias ? bias[col]   : 0.f;
                float b1 = bias ? bias[col+1] : 0.f;
                float2 v0 = make_float2(acc[mi][t][0] + b0, acc[mi][t][1] + b1);
                float2 v1 = make_float2(acc[mi][t][2] + b0, acc[mi][t][3] + b1);
                *(float2*)((float*)C + (size_t)row0      *EMB + col) = v0;
                *(float2*)((float*)C + (size_t)(row0 + 8)*EMB + col) = v1;
            }
        }
    }
}

__global__ void __launch_bounds__(256) gemm_qkv(
    const __half* __restrict__ x,
    const __half* __restrict__ Wq, const __half* __restrict__ Wk,
    const __half* __restrict__ Wv,
    __half* __restrict__ q, __half* __restrict__ k, __half* __restrict__ v)
{
    const __half* W = (blockIdx.z == 0) ? Wq : (blockIdx.z == 1) ? Wk : Wv;
    __half*       C = (blockIdx.z == 0) ? q  : (blockIdx.z == 1) ? k  : v;
    gemm_body(x, W, nullptr, C, 1);
}
__global__ void __launch_bounds__(256) gemm_out(
    const __half* __restrict__ A, const __half* __restrict__ W,
    const float* __restrict__ bias, float* __restrict__ C)
{
    gemm_body(A, W, bias, C, 0);
}

// ------------------------------------------------------------------
// Flash attention v2 (causal), fp16 operands / fp32 softmax+accum.
// grid(16, B*H), 128 threads. q-tile 128/block, warp 32 q rows.
// K/V double-buffered cp.async prefetch (next tile loads during compute).
// V row-major [s][d]; PV B-frags via ldmatrix.x4.trans.
// P relayout free (f16 C-frag == A-frag layout).
// ------------------------------------------------------------------
#define QS_B (128*RS)      // 18432
#define KS_B (64*RS)       //  9216
#define ATTN_SMEM (QS_B + 4*KS_B)   // 55296

__global__ void __launch_bounds__(128) attn_kernel(
    const __half* __restrict__ Q, const __half* __restrict__ K,
    const __half* __restrict__ V, __half* __restrict__ O)
{
    extern __shared__ uint32_t dyn[];
    const uint32_t sbase = (uint32_t)__cvta_generic_to_shared(dyn);
    const uint32_t qsa = sbase;

    const int tid  = threadIdx.x;
    const int lane = tid & 31, g = lane >> 2, tg = lane & 3;
    const int wq   = tid >> 5;
    const int qt   = gridDim.x - 1 - blockIdx.x;    // heavy blocks first
    const int b    = blockIdx.y >> 4;
    const int h    = blockIdx.y & 15;
    const int qbase = qt * 128;
    const float cs = 0.125f * 1.44269504088896f;    // 1/sqrt(64)*log2(e)

    const int alr = lane & 15, alk = (lane >> 4) * 16;

    const __half* Qg = Q + (size_t)(b*SEQ + qbase)*EMB + h*64;
    const __half* Kg = K + (size_t)(b*SEQ)*EMB + h*64;
    const __half* Vg = V + (size_t)(b*SEQ)*EMB + h*64;

    auto kbuf = [&](int s){ return sbase + QS_B + (uint32_t)s*KS_B; };
    auto vbuf = [&](int s){ return sbase + QS_B + 2*KS_B + (uint32_t)s*KS_B; };

    auto load_kv = [&](int jt, int s){
        uint32_t ka = kbuf(s), va = vbuf(s);
#pragma unroll
        for (int i = 0; i < 4; i++){
            int id = tid + i*128, r = id >> 3, c = id & 7;
            cpa16(ka + r*RS + c*16, Kg + (size_t)(jt*64 + r)*EMB + c*8);
        }
#pragma unroll
        for (int i = 0; i < 4; i++){
            int id = tid + i*128, r = id >> 3, c = id & 7;
            cpa16(va + r*RS + c*16, Vg + (size_t)(jt*64 + r)*EMB + c*8);
        }
    };

    // prologue: Q + tile 0 as one group
#pragma unroll
    for (int i = 0; i < 8; i++){
        int id = tid + i*128, r = id >> 3, c = id & 7;
        cpa16(qsa + r*RS + c*16, Qg + (size_t)r*EMB + c*8);
    }
    load_kv(0, 0);
    cpa_commit();

    float mrow[4], lrow[4];
#pragma unroll
    for (int i = 0; i < 4; i++){ mrow[i] = -1e30f; lrow[i] = 0.f; }
    float o[2][8][4];
#pragma unroll
    for (int mi = 0; mi < 2; mi++)
#pragma unroll
        for (int t = 0; t < 8; t++)
#pragma unroll
            for (int j = 0; j < 4; j++) o[mi][t][j] = 0.f;

    const int njt = 2*qt + 2;
    for (int jt = 0; jt < njt; jt++){
        const int s = jt & 1;
        __syncthreads();                 // all warps done with buffer s^1
        if (jt + 1 < njt){
            load_kv(jt + 1, s ^ 1);
            cpa_commit();
            cpa_wait1();                 // tile jt arrived (jt+1 in flight)
        } else {
            cpa_wait0();
        }
        __syncthreads();                 // tile jt visible to all warps

        const uint32_t ka = kbuf(s), va = vbuf(s);

        // ---- S = Q @ K^T : 32 q-rows x 64 keys per warp
        float sacc[2][8][4];
#pragma unroll
        for (int mi = 0; mi < 2; mi++)
#pragma unroll
            for (int t = 0; t < 8; t++)
#pragma unroll
                for (int j = 0; j < 4; j++) sacc[mi][t][j] = 0.f;
#pragma unroll
        for (int ks = 0; ks < 4; ks++){        // 4 x k16 over d
            uint32_t aq[2][4], bk[4][4];
#pragma unroll
            for (int mi = 0; mi < 2; mi++)
                ldsm4(aq[mi], qsa + (wq*32 + mi*16 + alr)*RS + ks*32 + alk);
#pragma unroll
            for (int p = 0; p < 4; p++)
                ldsm4(bk[p], ka + (p*16 + alr)*RS + ks*32 + alk);
#pragma unroll
            for (int mi = 0; mi < 2; mi++)
#pragma unroll
                for (int p = 0; p < 4; p++){
                    mma16(sacc[mi][2*p],   aq[mi], bk[p][0], bk[p][2]);
                    mma16(sacc[mi][2*p+1], aq[mi], bk[p][1], bk[p][3]);
                }
        }

        // ---- scale + (diagonal-only) causal mask + online softmax
        const bool need_mask = (jt >= 2*qt);
#pragma unroll
        for (int mi = 0; mi < 2; mi++){
            int q0 = qbase + wq*32 + mi*16 + g;
            int q1 = q0 + 8;
            float tm0 = -1e30f, tm1 = -1e30f;
#pragma unroll
            for (int t = 0; t < 8; t++){
                float* sc = sacc[mi][t];
                if (need_mask){
                    int jc = jt*64 + t*8 + 2*tg;
                    sc[0] = (jc     <= q0) ? sc[0]*cs : -1e30f;
                    sc[1] = (jc + 1 <= q0) ? sc[1]*cs : -1e30f;
                    sc[2] = (jc     <= q1) ? sc[2]*cs : -1e30f;
                    sc[3] = (jc + 1 <= q1) ? sc[3]*cs : -1e30f;
                } else {
                    sc[0] *= cs; sc[1] *= cs; sc[2] *= cs; sc[3] *= cs;
                }
                tm0 = fmaxf(tm0, fmaxf(sc[0], sc[1]));
                tm1 = fmaxf(tm1, fmaxf(sc[2], sc[3]));
            }
            tm0 = fmaxf(tm0, __shfl_xor_sync(0xffffffffu, tm0, 1));
            tm0 = fmaxf(tm0, __shfl_xor_sync(0xffffffffu, tm0, 2));
            tm1 = fmaxf(tm1, __shfl_xor_sync(0xffffffffu, tm1, 1));
            tm1 = fmaxf(tm1, __shfl_xor_sync(0xffffffffu, tm1, 2));
            float mn0 = fmaxf(mrow[mi*2],     tm0);
            float mn1 = fmaxf(mrow[mi*2 + 1], tm1);
            float a0  = ex2f(mrow[mi*2]     - mn0);
            float a1  = ex2f(mrow[mi*2 + 1] - mn1);
            float rs0 = 0.f, rs1 = 0.f;
#pragma unroll
            for (int t = 0; t < 8; t++){
                float* sc = sacc[mi][t];
                sc[0] = ex2f(sc[0] - mn0);
                sc[1] = ex2f(sc[1] - mn0);
                sc[2] = ex2f(sc[2] - mn1);
                sc[3] = ex2f(sc[3] - mn1);
                rs0 += sc[0] + sc[1];
                rs1 += sc[2] + sc[3];
            }
            rs0 += __shfl_xor_sync(0xffffffffu, rs0, 1);
            rs0 += __shfl_xor_sync(0xffffffffu, rs0, 2);
            rs1 += __shfl_xor_sync(0xffffffffu, rs1, 1);
            rs1 += __shfl_xor_sync(0xffffffffu, rs1, 2);
            lrow[mi*2]     = lrow[mi*2]*a0     + rs0;
            lrow[mi*2 + 1] = lrow[mi*2 + 1]*a1 + rs1;
            mrow[mi*2]     = mn0;
            mrow[mi*2 + 1] = mn1;
#pragma unroll
            for (int t = 0; t < 8; t++){
                o[mi][t][0] *= a0; o[mi][t][1] *= a0;
                o[mi][t][2] *= a1; o[mi][t][3] *= a1;
            }
        }

        // ---- O += P @ V : B-frags via ldmatrix.trans on row-major V
#pragma unroll
        for (int ks = 0; ks < 4; ks++){        // 4 x k16 over keys
#pragma unroll
            for (int p = 0; p < 4; p++){       // d pairs of 16
                uint32_t bv[4];
                ldsm4t(bv, va + (ks*16 + alr)*RS + p*32 + alk);
#pragma unroll
                for (int mi = 0; mi < 2; mi++){
                    uint32_t av[4];
                    av[0] = ph2(sacc[mi][2*ks][0],   sacc[mi][2*ks][1]);
                    av[1] = ph2(sacc[mi][2*ks][2],   sacc[mi][2*ks][3]);
                    av[2] = ph2(sacc[mi][2*ks+1][0], sacc[mi][2*ks+1][1]);
                    av[3] = ph2(sacc[mi][2*ks+1][2], sacc[mi][2*ks+1][3]);
                    mma16(o[mi][2*p],   av, bv[0], bv[1]);
                    mma16(o[mi][2*p+1], av, bv[2], bv[3]);
                }
            }
        }
    }

    // ---- epilogue: normalize, store half (feeds final GEMM)
#pragma unroll
    for (int mi = 0; mi < 2; mi++){
        float i0 = 1.f / lrow[mi*2];
        float i1 = 1.f / lrow[mi*2 + 1];
        size_t q0 = (size_t)(b*SEQ + qbase + wq*32 + mi*16 + g);
#pragma unroll
        for (int t = 0; t < 8; t++){
            int col = h*64 + t*8 + 2*tg;
            __half2 h0 = __floats2half2_rn(o[mi][t][0]*i0, o[mi][t][1]*i0);
            __half2 h1 = __floats2half2_rn(o[mi][t][2]*i1, o[mi][t][3]*i1);
            *(__half2*)(O + q0*EMB + col)       = h0;
            *(__half2*)(O + (q0 + 8)*EMB + col) = h1;
        }
    }
}

// ------------------------------------------------------------------
extern "C" void kernel_launch(void* const* d_in, const int* in_sizes, int n_in,
                              void* d_out, int out_size)
{
    const float* x  = (const float*)d_in[0];
    const float* Wq = (const float*)d_in[1];
    const float* Wk = (const float*)d_in[2];
    const float* Wv = (const float*)d_in[3];
    const float* Wo = (const float*)d_in[4];
    const float* bo = (const float*)d_in[5];
    float* out = (float*)d_out;

    __half *q, *k, *v, *ao, *xc, *wq, *wk, *wv, *wo;
    cudaGetSymbolAddress((void**)&q,  g_q);
    cudaGetSymbolAddress((void**)&k,  g_k);
    cudaGetSymbolAddress((void**)&v,  g_v);
    cudaGetSymbolAddress((void**)&ao, g_ao);
    cudaGetSymbolAddress((void**)&xc, g_xc);
    cudaGetSymbolAddress((void**)&wq, g_wq);
    cudaGetSymbolAddress((void**)&wk, g_wk);
    cudaGetSymbolAddress((void**)&wv, g_wv);
    cudaGetSymbolAddress((void**)&wo, g_wo);

    cudaFuncSetAttribute(gemm_qkv,
                         cudaFuncAttributeMaxDynamicSharedMemorySize, GEMM_SMEM);
    cudaFuncSetAttribute(gemm_out,
                         cudaFuncAttributeMaxDynamicSharedMemorySize, GEMM_SMEM);
    cudaFuncSetAttribute(attn_kernel,
                         cudaFuncAttributeMaxDynamicSharedMemorySize, ATTN_SMEM);

    // pre-round inputs to fp16
    const int nx4 = MR*EMB/4, nw4 = EMB*EMB/4;
    cvt_f2h<<<(nx4+255)/256, 256>>>((const float4*)x, (uint2*)xc, nx4);
    dim3 gw((nw4+255)/256, 4);
    cvt_f2h4<<<gw, 256>>>((const float4*)Wq, (const float4*)Wk,
                          (const float4*)Wv, (const float4*)Wo,
                          (uint2*)wq, (uint2*)wk, (uint2*)wv, (uint2*)wo, nw4);

    dim3 gq(EMB/256, MR/128, 3);          // 4 x 64 x 3
    gemm_qkv<<<gq, 256, GEMM_SMEM>>>(xc, wq, wk, wv, q, k, v);

    dim3 ga(SEQ/128, NB*NH);              // 16 x 64
    attn_kernel<<<ga, 128, ATTN_SMEM>>>(q, k, v, ao);

    dim3 go(EMB/256, MR/128);             // 4 x 64
    gemm_out<<<go, 256, GEMM_SMEM>>>(ao, wo, bo, out);
}

// round 11
// speedup vs baseline: 2.5837x; 1.0182x over previous
#include <cuda_runtime.h>
#include <cuda_fp16.h>
#include <cstdint>
#include <cstddef>

#define EMB 1024
#define SEQ 2048
#define NB  4
#define NH  16
#define MR  (NB*SEQ)   // 8192 rows

// static device scratch (allocation-guard safe) — fp16 activations/weights
__device__ __half g_q [(size_t)MR*EMB];
__device__ __half g_k [(size_t)MR*EMB];
__device__ __half g_v [(size_t)MR*EMB];
__device__ __half g_ao[(size_t)MR*EMB];
__device__ __half g_xc[(size_t)MR*EMB];
__device__ __half g_wq[(size_t)EMB*EMB];
__device__ __half g_wk[(size_t)EMB*EMB];
__device__ __half g_wv[(size_t)EMB*EMB];
__device__ __half g_wo[(size_t)EMB*EMB];

__device__ __forceinline__ float ex2f(float x){
    float y; asm("ex2.approx.ftz.f32 %0, %1;" : "=f"(y) : "f"(x)); return y;
}
// D += A*B : m16n8k16 fp16 in / fp32 accum.
// A frag: a0=(g,2tg..) a1=(g+8,2tg..) a2=(g,2tg+8..) a3=(g+8,2tg+8..)
// B frag: b0=(k=2tg..,n=g) b1=(k=2tg+8..,n=g)
// C frag: c0=(g,2tg) c1=(g,2tg+1) c2=(g+8,2tg) c3=(g+8,2tg+1)
__device__ __forceinline__ void mma16(float* d, const uint32_t* a,
                                      uint32_t b0, uint32_t b1){
    asm volatile(
      "mma.sync.aligned.m16n8k16.row.col.f32.f16.f16.f32 "
      "{%0,%1,%2,%3}, {%4,%5,%6,%7}, {%8,%9}, {%0,%1,%2,%3};\n"
      : "+f"(d[0]), "+f"(d[1]), "+f"(d[2]), "+f"(d[3])
      : "r"(a[0]), "r"(a[1]), "r"(a[2]), "r"(a[3]), "r"(b0), "r"(b1));
}
__device__ __forceinline__ void ldsm4(uint32_t* r, uint32_t saddr){
    asm volatile("ldmatrix.sync.aligned.m8n8.x4.shared.b16 {%0,%1,%2,%3}, [%4];"
        : "=r"(r[0]), "=r"(r[1]), "=r"(r[2]), "=r"(r[3]) : "r"(saddr));
}
__device__ __forceinline__ void ldsm4t(uint32_t* r, uint32_t saddr){
    asm volatile("ldmatrix.sync.aligned.m8n8.x4.trans.shared.b16 {%0,%1,%2,%3}, [%4];"
        : "=r"(r[0]), "=r"(r[1]), "=r"(r[2]), "=r"(r[3]) : "r"(saddr));
}
__device__ __forceinline__ void cpa16(uint32_t saddr, const void* g){
    asm volatile("cp.async.ca.shared.global [%0], [%1], 16;" :: "r"(saddr), "l"(g));
}
__device__ __forceinline__ void cpa_commit(){ asm volatile("cp.async.commit_group;"); }
__device__ __forceinline__ void cpa_wait0(){ asm volatile("cp.async.wait_group 0;"); }
__device__ __forceinline__ void cpa_wait1(){ asm volatile("cp.async.wait_group 1;"); }
__device__ __forceinline__ uint32_t ph2(float lo, float hi){
    __half2 t = __floats2half2_rn(lo, hi);
    return *(uint32_t*)&t;
}

// ------------------------------------------------------------------
// fp32 -> fp16 pre-round: x (single) and 4 weights (grid.y)
// ------------------------------------------------------------------
__global__ void __launch_bounds__(256) cvt_f2h(
    const float4* __restrict__ src, uint2* __restrict__ dst, int n4)
{
    int i = blockIdx.x*256 + threadIdx.x;
    if (i < n4){
        float4 v = src[i];
        uint2 o; o.x = ph2(v.x, v.y); o.y = ph2(v.z, v.w);
        dst[i] = o;
    }
}
__global__ void __launch_bounds__(256) cvt_f2h4(
    const float4* __restrict__ s0, const float4* __restrict__ s1,
    const float4* __restrict__ s2, const float4* __restrict__ s3,
    uint2* __restrict__ d0, uint2* __restrict__ d1,
    uint2* __restrict__ d2, uint2* __restrict__ d3, int n4)
{
    const float4* s = (blockIdx.y==0)?s0:(blockIdx.y==1)?s1:(blockIdx.y==2)?s2:s3;
    uint2*        d = (blockIdx.y==0)?d0:(blockIdx.y==1)?d1:(blockIdx.y==2)?d2:d3;
    int i = blockIdx.x*256 + threadIdx.x;
    if (i < n4){
        float4 v = s[i];
        uint2 o; o.x = ph2(v.x, v.y); o.y = ph2(v.z, v.w);
        d[i] = o;
    }
}

// ------------------------------------------------------------------
// fp16 GEMM (R8-proven, unchanged): C[M,N] = A[M,K] @ W[N,K]^T (+bias).
// Block 128(m) x 256(n), BK=64 halves, 256 thr, warps 2(m)x4(n) -> 64x64.
// cp.async double-buffered; row stride 144B (9x16B): rows r..r+7 hit
// distinct 16B bank groups => conflict-free ldmatrix.
// ------------------------------------------------------------------
#define RS   144                              // row stride bytes
#define GA_B (128*RS)                         // 18432
#define GB_B (256*RS)                         // 36864
#define GSTG (GA_B + GB_B)                    // 55296
#define GEMM_SMEM (2*GSTG)                    // 110592

__device__ __forceinline__ void gemm_body(
    const __half* __restrict__ A, const __half* __restrict__ W,
    const float* __restrict__ bias, void* __restrict__ C, int out_half)
{
    extern __shared__ uint32_t sh[];
    const uint32_t sbase = (uint32_t)__cvta_generic_to_shared(sh);

    const int tid  = threadIdx.x;
    const int lane = tid & 31, g = lane >> 2, tg = lane & 3;
    const int wid  = tid >> 5;
    const int wm   = (wid & 1) * 64;
    const int wn   = (wid >> 1) * 64;
    const int bm   = blockIdx.y * 128;
    const int bn   = blockIdx.x * 256;

    const int alr = lane & 15;                // ldsm row within 16
    const int alk = (lane >> 4) * 16;         // ldsm 16B col select

    const __half* Ag = A + (size_t)bm*EMB;
    const __half* Wg = W + (size_t)bn*EMB;

    float acc[4][8][4];
#pragma unroll
    for (int mi = 0; mi < 4; mi++)
#pragma unroll
        for (int t = 0; t < 8; t++)
#pragma unroll
            for (int j = 0; j < 4; j++) acc[mi][t][j] = 0.f;

    auto stage = [&](int kt, int s){
        const uint32_t sa = sbase + (uint32_t)s*GSTG;
        const uint32_t sb = sa + GA_B;
#pragma unroll
        for (int i = 0; i < 4; i++){           // A: 128 rows x 8 chunks
            int id = tid + i*256, r = id >> 3, c = id & 7;
            cpa16(sa + r*RS + c*16, Ag + (size_t)r*EMB + kt*64 + c*8);
        }
#pragma unroll
        for (int i = 0; i < 8; i++){           // B: 256 rows x 8 chunks
            int id = tid + i*256, r = id >> 3, c = id & 7;
            cpa16(sb + r*RS + c*16, Wg + (size_t)r*EMB + kt*64 + c*8);
        }
        cpa_commit();
    };

    stage(0, 0);
    stage(1, 1);

    const int nk = EMB/64;   // 16
    for (int kt = 0; kt < nk; kt++){
        const int s = kt & 1;
        if (kt + 1 < nk) cpa_wait1(); else cpa_wait0();
        __syncthreads();
        const uint32_t sa = sbase + (uint32_t)s*GSTG;
        const uint32_t sb = sa + GA_B;
#pragma unroll
        for (int kk = 0; kk < 4; kk++){        // 4 x k16
            uint32_t af[4][4], bf[4][4];
#pragma unroll
            for (int mi = 0; mi < 4; mi++)
                ldsm4(af[mi], sa + (wm + mi*16 + alr)*RS + kk*32 + alk);
#pragma unroll
            for (int p = 0; p < 4; p++)
                ldsm4(bf[p], sb + (wn + p*16 + alr)*RS + kk*32 + alk);
#pragma unroll
            for (int mi = 0; mi < 4; mi++)
#pragma unroll
                for (int p = 0; p < 4; p++){
                    mma16(acc[mi][2*p],   af[mi], bf[p][0], bf[p][2]);
                    mma16(acc[mi][2*p+1], af[mi], bf[p][1], bf[p][3]);
                }
        }
        __syncthreads();
        if (kt + 2 < nk) stage(kt + 2, s);
    }

    // epilogue
#pragma unroll
    for (int mi = 0; mi < 4; mi++){
#pragma unroll
        for (int t = 0; t < 8; t++){
            int col  = bn + wn + t*8 + 2*tg;
            int row0 = bm + wm + mi*16 + g;
            if (out_half){
                __half2 h0 = __floats2half2_rn(acc[mi][t][0], acc[mi][t][1]);
                __half2 h1 = __floats2half2_rn(acc[mi][t][2], acc[mi][t][3]);
                *(__half2*)((__half*)C + (size_t)row0      *EMB + col) = h0;
                *(__half2*)((__half*)C + (size_t)(row0 + 8)*EMB + col) = h1;
            } else {
                float b0 = bias ? bias[col]   : 0.f;
                float b1 = bias ? bias[col+1] : 0.f;
                float2 v0 = make_float2(acc[mi][t][0] + b0, acc[mi][t][1] + b1);
                float2 v1 = make_float2(acc[mi][t][2] + b0, acc[mi][t][3] + b1);
                *(float2*)((float*)C + (size_t)row0      *EMB + col) = v0;
                *(float2*)((float*)C + (size_t)(row0 + 8)*EMB + col) = v1;
            }
        }
    }
}

__global__ void __launch_bounds__(256) gemm_qkv(
    const __half* __restrict__ x,
    const __half* __restrict__ Wq, const __half* __restrict__ Wk,
    const __half* __restrict__ Wv,
    __half* __restrict__ q, __half* __restrict__ k, __half* __restrict__ v)
{
    const __half* W = (blockIdx.z == 0) ? Wq : (blockIdx.z == 1) ? Wk : Wv;
    __half*       C = (blockIdx.z == 0) ? q  : (blockIdx.z == 1) ? k  : v;
    gemm_body(x, W, nullptr, C, 1);
}
__global__ void __launch_bounds__(256) gemm_out(
    const __half* __restrict__ A, const __half* __restrict__ W,
    const float* __restrict__ bias, float* __restrict__ C)
{
    gemm_body(A, W, bias, C, 0);
}

// ------------------------------------------------------------------
// Flash attention v2 (causal), fp16 operands / fp32 softmax+accum.
// grid(16, B*H), 256 threads (8 warps), q-tile 128, 16 q-rows/warp.
// __launch_bounds__(256,2) caps regs at 128 -> 2 CTAs/SM = 16 warps/SM
// (4 per scheduler) to hide the softmax dependency chain.
// K/V double-buffered cp.async prefetch; V row-major, PV B-frags via
// ldmatrix.x4.trans; P relayout free (f16 C-frag == A-frag layout).
// ------------------------------------------------------------------
#define QS_B (128*RS)      // 18432
#define KS_B (64*RS)       //  9216
#define ATTN_SMEM (QS_B + 4*KS_B)   // 55296

__global__ void __launch_bounds__(256, 2) attn_kernel(
    const __half* __restrict__ Q, const __half* __restrict__ K,
    const __half* __restrict__ V, __half* __restrict__ O)
{
    extern __shared__ uint32_t dyn[];
    const uint32_t sbase = (uint32_t)__cvta_generic_to_shared(dyn);
    const uint32_t qsa = sbase;

    const int tid  = threadIdx.x;
    const int lane = tid & 31, g = lane >> 2, tg = lane & 3;
    const int wq   = tid >> 5;                      // 0..7, 16 q rows each
    const int qt   = gridDim.x - 1 - blockIdx.x;    // heavy blocks first
    const int b    = blockIdx.y >> 4;
    const int h    = blockIdx.y & 15;
    const int qbase = qt * 128;
    const float cs = 0.125f * 1.44269504088896f;    // 1/sqrt(64)*log2(e)

    const int alr = lane & 15, alk = (lane >> 4) * 16;

    const __half* Qg = Q + (size_t)(b*SEQ + qbase)*EMB + h*64;
    const __half* Kg = K + (size_t)(b*SEQ)*EMB + h*64;
    const __half* Vg = V + (size_t)(b*SEQ)*EMB + h*64;

    auto kbuf = [&](int s){ return sbase + QS_B + (uint32_t)s*KS_B; };
    auto vbuf = [&](int s){ return sbase + QS_B + 2*KS_B + (uint32_t)s*KS_B; };

    auto load_kv = [&](int jt, int s){
        uint32_t ka = kbuf(s), va = vbuf(s);
#pragma unroll
        for (int i = 0; i < 2; i++){
            int id = tid + i*256, r = id >> 3, c = id & 7;
            cpa16(ka + r*RS + c*16, Kg + (size_t)(jt*64 + r)*EMB + c*8);
        }
#pragma unroll
        for (int i = 0; i < 2; i++){
            int id = tid + i*256, r = id >> 3, c = id & 7;
            cpa16(va + r*RS + c*16, Vg + (size_t)(jt*64 + r)*EMB + c*8);
        }
    };

    // prologue: Q + tile 0 as one group
#pragma unroll
    for (int i = 0; i < 4; i++){
        int id = tid + i*256, r = id >> 3, c = id & 7;
        cpa16(qsa + r*RS + c*16, Qg + (size_t)r*EMB + c*8);
    }
    load_kv(0, 0);
    cpa_commit();

    float m0 = -1e30f, m1 = -1e30f, l0 = 0.f, l1 = 0.f;
    float o[8][4];
#pragma unroll
    for (int t = 0; t < 8; t++)
#pragma unroll
        for (int j = 0; j < 4; j++) o[t][j] = 0.f;

    const int q0r = qbase + wq*16 + g;     // this thread's 2 q rows
    const int q1r = q0r + 8;

    const int njt = 2*qt + 2;
    for (int jt = 0; jt < njt; jt++){
        const int s = jt & 1;
        __syncthreads();                 // all warps done with buffer s^1
        if (jt + 1 < njt){
            load_kv(jt + 1, s ^ 1);
            cpa_commit();
            cpa_wait1();                 // tile jt arrived (jt+1 in flight)
        } else {
            cpa_wait0();
        }
        __syncthreads();                 // tile jt visible to all warps

        const uint32_t ka = kbuf(s), va = vbuf(s);

        // ---- S = Q @ K^T : 16 q-rows x 64 keys per warp
        float sacc[8][4];
#pragma unroll
        for (int t = 0; t < 8; t++)
#pragma unroll
            for (int j = 0; j < 4; j++) sacc[t][j] = 0.f;
#pragma unroll
        for (int ks = 0; ks < 4; ks++){        // 4 x k16 over d
            uint32_t aq[4], bk[4][4];
            ldsm4(aq, qsa + (wq*16 + alr)*RS + ks*32 + alk);
#pragma unroll
            for (int p = 0; p < 4; p++)
                ldsm4(bk[p], ka + (p*16 + alr)*RS + ks*32 + alk);
#pragma unroll
            for (int p = 0; p < 4; p++){
                mma16(sacc[2*p],   aq, bk[p][0], bk[p][2]);
                mma16(sacc[2*p+1], aq, bk[p][1], bk[p][3]);
            }
        }

        // ---- scale + (diagonal-only) causal mask + online softmax
        const bool need_mask = (jt >= 2*qt);
        {
            float tm0 = -1e30f, tm1 = -1e30f;
#pragma unroll
            for (int t = 0; t < 8; t++){
                float* sc = sacc[t];
                if (need_mask){
                    int jc = jt*64 + t*8 + 2*tg;
                    sc[0] = (jc     <= q0r) ? sc[0]*cs : -1e30f;
                    sc[1] = (jc + 1 <= q0r) ? sc[1]*cs : -1e30f;
                    sc[2] = (jc     <= q1r) ? sc[2]*cs : -1e30f;
                    sc[3] = (jc + 1 <= q1r) ? sc[3]*cs : -1e30f;
                } else {
                    sc[0] *= cs; sc[1] *= cs; sc[2] *= cs; sc[3] *= cs;
                }
                tm0 = fmaxf(tm0, fmaxf(sc[0], sc[1]));
                tm1 = fmaxf(tm1, fmaxf(sc[2], sc[3]));
            }
            tm0 = fmaxf(tm0, __shfl_xor_sync(0xffffffffu, tm0, 1));
            tm0 = fmaxf(tm0, __shfl_xor_sync(0xffffffffu, tm0, 2));
            tm1 = fmaxf(tm1, __shfl_xor_sync(0xffffffffu, tm1, 1));
            tm1 = fmaxf(tm1, __shfl_xor_sync(0xffffffffu, tm1, 2));
            float mn0 = fmaxf(m0, tm0);
            float mn1 = fmaxf(m1, tm1);
            float a0  = ex2f(m0 - mn0);
            float a1  = ex2f(m1 - mn1);
            float rs0 = 0.f, rs1 = 0.f;
#pragma unroll
            for (int t = 0; t < 8; t++){
                float* sc = sacc[t];
                sc[0] = ex2f(sc[0] - mn0);
                sc[1] = ex2f(sc[1] - mn0);
                sc[2] = ex2f(sc[2] - mn1);
                sc[3] = ex2f(sc[3] - mn1);
                rs0 += sc[0] + sc[1];
                rs1 += sc[2] + sc[3];
            }
            rs0 += __shfl_xor_sync(0xffffffffu, rs0, 1);
            rs0 += __shfl_xor_sync(0xffffffffu, rs0, 2);
            rs1 += __shfl_xor_sync(0xffffffffu, rs1, 1);
            rs1 += __shfl_xor_sync(0xffffffffu, rs1, 2);
            l0 = l0*a0 + rs0;
            l1 = l1*a1 + rs1;
            m0 = mn0; m1 = mn1;
#pragma unroll
            for (int t = 0; t < 8; t++){
                o[t][0] *= a0; o[t][1] *= a0;
                o[t][2] *= a1; o[t][3] *= a1;
            }
        }

        // ---- O += P @ V : B-frags via ldmatrix.trans on row-major V
#pragma unroll
        for (int ks = 0; ks < 4; ks++){        // 4 x k16 over keys
            uint32_t av[4];                    // A-frag from S C-frags (hoisted)
            av[0] = ph2(sacc[2*ks][0],   sacc[2*ks][1]);
            av[1] = ph2(sacc[2*ks][2],   sacc[2*ks][3]);
            av[2] = ph2(sacc[2*ks+1][0], sacc[2*ks+1][1]);
            av[3] = ph2(sacc[2*ks+1][2], sacc[2*ks+1][3]);
#pragma unroll
            for (int p = 0; p < 4; p++){       // d pairs of 16
                uint32_t bv[4];
                ldsm4t(bv, va + (ks*16 + alr)*RS + p*32 + alk);
                mma16(o[2*p],   av, bv[0], bv[1]);
                mma16(o[2*p+1], av, bv[2], bv[3]);
            }
        }
    }

    // ---- epilogue: normalize, store half (feeds final GEMM)
    {
        float i0 = 1.f / l0;
        float i1 = 1.f / l1;
        size_t r0 = (size_t)(b*SEQ + q0r);
#pragma unroll
        for (int t = 0; t < 8; t++){
            int col = h*64 + t*8 + 2*tg;
            __half2 h0 = __floats2half2_rn(o[t][0]*i0, o[t][1]*i0);
            __half2 h1 = __floats2half2_rn(o[t][2]*i1, o[t][3]*i1);
            *(__half2*)(O + r0*EMB + col)       = h0;
            *(__half2*)(O + (r0 + 8)*EMB + col) = h1;
        }
    }
}

// ------------------------------------------------------------------
extern "C" void kernel_launch(void* const* d_in, const int* in_sizes, int n_in,
                              void* d_out, int out_size)
{
    const float* x  = (const float*)d_in[0];
    const float* Wq = (const float*)d_in[1];
    const float* Wk = (const float*)d_in[2];
    const float* Wv = (const float*)d_in[3];
    const float* Wo = (const float*)d_in[4];
    const float* bo = (const float*)d_in[5];
    float* out = (float*)d_out;

    __half *q, *k, *v, *ao, *xc, *wq, *wk, *wv, *wo;
    cudaGetSymbolAddress((void**)&q,  g_q);
    cudaGetSymbolAddress((void**)&k,  g_k);
    cudaGetSymbolAddress((void**)&v,  g_v);
    cudaGetSymbolAddress((void**)&ao, g_ao);
    cudaGetSymbolAddress((void**)&xc, g_xc);
    cudaGetSymbolAddress((void**)&wq, g_wq);
    cudaGetSymbolAddress((void**)&wk, g_wk);
    cudaGetSymbolAddress((void**)&wv, g_wv);
    cudaGetSymbolAddress((void**)&wo, g_wo);

    cudaFuncSetAttribute(gemm_qkv,
                         cudaFuncAttributeMaxDynamicSharedMemorySize, GEMM_SMEM);
    cudaFuncSetAttribute(gemm_out,
                         cudaFuncAttributeMaxDynamicSharedMemorySize, GEMM_SMEM);
    cudaFuncSetAttribute(attn_kernel,
                         cudaFuncAttributeMaxDynamicSharedMemorySize, ATTN_SMEM);

    // pre-round inputs to fp16
    const int nx4 = MR*EMB/4, nw4 = EMB*EMB/4;
    cvt_f2h<<<(nx4+255)/256, 256>>>((const float4*)x, (uint2*)xc, nx4);
    dim3 gw((nw4+255)/256, 4);
    cvt_f2h4<<<gw, 256>>>((const float4*)Wq, (const float4*)Wk,
                          (const float4*)Wv, (const float4*)Wo,
                          (uint2*)wq, (uint2*)wk, (uint2*)wv, (uint2*)wo, nw4);

    dim3 gq(EMB/256, MR/128, 3);          // 4 x 64 x 3
    gemm_qkv<<<gq, 256, GEMM_SMEM>>>(xc, wq, wk, wv, q, k, v);

    dim3 ga(SEQ/128, NB*NH);              // 16 x 64
    attn_kernel<<<ga, 256, ATTN_SMEM>>>(q, k, v, ao);

    dim3 go(EMB/256, MR/128);             // 4 x 64
    gemm_out<<<go, 256, GEMM_SMEM>>>(ao, wo, bo, out);
}

// round 12
// speedup vs baseline: 2.7613x; 1.0687x over previous
#include <cuda_runtime.h>
#include <cuda_fp16.h>
#include <cstdint>
#include <cstddef>

#define EMB 1024
#define SEQ 2048
#define NB  4
#define NH  16
#define MR  (NB*SEQ)   // 8192 rows

// static device scratch (allocation-guard safe) — fp16 activations/weights
__device__ __half g_q [(size_t)MR*EMB];
__device__ __half g_k [(size_t)MR*EMB];
__device__ __half g_v [(size_t)MR*EMB];
__device__ __half g_ao[(size_t)MR*EMB];
__device__ __half g_xc[(size_t)MR*EMB];
__device__ __half g_wq[(size_t)EMB*EMB];
__device__ __half g_wk[(size_t)EMB*EMB];
__device__ __half g_wv[(size_t)EMB*EMB];
__device__ __half g_wo[(size_t)EMB*EMB];

__device__ __forceinline__ float ex2f(float x){
    float y; asm("ex2.approx.ftz.f32 %0, %1;" : "=f"(y) : "f"(x)); return y;
}
// D += A*B : m16n8k16 fp16 in / fp32 accum.
// A frag: a0=(g,2tg..) a1=(g+8,2tg..) a2=(g,2tg+8..) a3=(g+8,2tg+8..)
// B frag: b0=(k=2tg..,n=g) b1=(k=2tg+8..,n=g)
// C frag: c0=(g,2tg) c1=(g,2tg+1) c2=(g+8,2tg) c3=(g+8,2tg+1)
__device__ __forceinline__ void mma16(float* d, const uint32_t* a,
                                      uint32_t b0, uint32_t b1){
    asm volatile(
      "mma.sync.aligned.m16n8k16.row.col.f32.f16.f16.f32 "
      "{%0,%1,%2,%3}, {%4,%5,%6,%7}, {%8,%9}, {%0,%1,%2,%3};\n"
      : "+f"(d[0]), "+f"(d[1]), "+f"(d[2]), "+f"(d[3])
      : "r"(a[0]), "r"(a[1]), "r"(a[2]), "r"(a[3]), "r"(b0), "r"(b1));
}
__device__ __forceinline__ void ldsm4(uint32_t* r, uint32_t saddr){
    asm volatile("ldmatrix.sync.aligned.m8n8.x4.shared.b16 {%0,%1,%2,%3}, [%4];"
        : "=r"(r[0]), "=r"(r[1]), "=r"(r[2]), "=r"(r[3]) : "r"(saddr));
}
__device__ __forceinline__ void ldsm4t(uint32_t* r, uint32_t saddr){
    asm volatile("ldmatrix.sync.aligned.m8n8.x4.trans.shared.b16 {%0,%1,%2,%3}, [%4];"
        : "=r"(r[0]), "=r"(r[1]), "=r"(r[2]), "=r"(r[3]) : "r"(saddr));
}
__device__ __forceinline__ void cpa16(uint32_t saddr, const void* g){
    asm volatile("cp.async.ca.shared.global [%0], [%1], 16;" :: "r"(saddr), "l"(g));
}
__device__ __forceinline__ void cpa_commit(){ asm volatile("cp.async.commit_group;"); }
__device__ __forceinline__ void cpa_wait0(){ asm volatile("cp.async.wait_group 0;"); }
__device__ __forceinline__ void cpa_wait1(){ asm volatile("cp.async.wait_group 1;"); }
__device__ __forceinline__ uint32_t ph2(float lo, float hi){
    __half2 t = __floats2half2_rn(lo, hi);
    return *(uint32_t*)&t;
}

// ------------------------------------------------------------------
// fp32 -> fp16 pre-round: x (single) and 4 weights (grid.y)
// ------------------------------------------------------------------
__global__ void __launch_bounds__(256) cvt_f2h(
    const float4* __restrict__ src, uint2* __restrict__ dst, int n4)
{
    int i = blockIdx.x*256 + threadIdx.x;
    if (i < n4){
        float4 v = src[i];
        uint2 o; o.x = ph2(v.x, v.y); o.y = ph2(v.z, v.w);
        dst[i] = o;
    }
}
__global__ void __launch_bounds__(256) cvt_f2h4(
    const float4* __restrict__ s0, const float4* __restrict__ s1,
    const float4* __restrict__ s2, const float4* __restrict__ s3,
    uint2* __restrict__ d0, uint2* __restrict__ d1,
    uint2* __restrict__ d2, uint2* __restrict__ d3, int n4)
{
    const float4* s = (blockIdx.y==0)?s0:(blockIdx.y==1)?s1:(blockIdx.y==2)?s2:s3;
    uint2*        d = (blockIdx.y==0)?d0:(blockIdx.y==1)?d1:(blockIdx.y==2)?d2:d3;
    int i = blockIdx.x*256 + threadIdx.x;
    if (i < n4){
        float4 v = s[i];
        uint2 o; o.x = ph2(v.x, v.y); o.y = ph2(v.z, v.w);
        d[i] = o;
    }
}

// ------------------------------------------------------------------
// fp16 GEMM: C[M,N] = A[M,K] @ W[N,K]^T (+bias). M=8192, N=K=1024.
// Block 128(m) x 128(n), BK=64 halves, 256 thr, warps 2(m)x4(n) -> 64x32.
// acc 64 regs -> __launch_bounds__(256,2) gives 2 CTAs/SM (4 warps/SMSP).
// cp.async double-buffered; row stride 144B: conflict-free ldmatrix.
// ------------------------------------------------------------------
#define RS   144                              // row stride bytes
#define GT_B (128*RS)                         // 18432 per operand tile
#define GSTG (2*GT_B)                         // 36864
#define GEMM_SMEM (2*GSTG)                    // 73728

__device__ __forceinline__ void gemm_body(
    const __half* __restrict__ A, const __half* __restrict__ W,
    const float* __restrict__ bias, void* __restrict__ C, int out_half)
{
    extern __shared__ uint32_t sh[];
    const uint32_t sbase = (uint32_t)__cvta_generic_to_shared(sh);

    const int tid  = threadIdx.x;
    const int lane = tid & 31, g = lane >> 2, tg = lane & 3;
    const int wid  = tid >> 5;
    const int wm   = (wid & 1) * 64;
    const int wn   = (wid >> 1) * 32;
    const int bm   = blockIdx.y * 128;
    const int bn   = blockIdx.x * 128;

    const int alr = lane & 15;                // ldsm row within 16
    const int alk = (lane >> 4) * 16;         // ldsm 16B col select

    const __half* Ag = A + (size_t)bm*EMB;
    const __half* Wg = W + (size_t)bn*EMB;

    float acc[4][4][4];
#pragma unroll
    for (int mi = 0; mi < 4; mi++)
#pragma unroll
        for (int t = 0; t < 4; t++)
#pragma unroll
            for (int j = 0; j < 4; j++) acc[mi][t][j] = 0.f;

    auto stage = [&](int kt, int s){
        const uint32_t sa = sbase + (uint32_t)s*GSTG;
        const uint32_t sb = sa + GT_B;
#pragma unroll
        for (int i = 0; i < 4; i++){           // A: 128 rows x 8 chunks
            int id = tid + i*256, r = id >> 3, c = id & 7;
            cpa16(sa + r*RS + c*16, Ag + (size_t)r*EMB + kt*64 + c*8);
        }
#pragma unroll
        for (int i = 0; i < 4; i++){           // B: 128 rows x 8 chunks
            int id = tid + i*256, r = id >> 3, c = id & 7;
            cpa16(sb + r*RS + c*16, Wg + (size_t)r*EMB + kt*64 + c*8);
        }
        cpa_commit();
    };

    stage(0, 0);
    stage(1, 1);

    const int nk = EMB/64;   // 16
    for (int kt = 0; kt < nk; kt++){
        const int s = kt & 1;
        if (kt + 1 < nk) cpa_wait1(); else cpa_wait0();
        __syncthreads();
        const uint32_t sa = sbase + (uint32_t)s*GSTG;
        const uint32_t sb = sa + GT_B;
#pragma unroll
        for (int kk = 0; kk < 4; kk++){        // 4 x k16
            uint32_t af[4][4], bf[2][4];
#pragma unroll
            for (int mi = 0; mi < 4; mi++)
                ldsm4(af[mi], sa + (wm + mi*16 + alr)*RS + kk*32 + alk);
#pragma unroll
            for (int p = 0; p < 2; p++)
                ldsm4(bf[p], sb + (wn + p*16 + alr)*RS + kk*32 + alk);
#pragma unroll
            for (int mi = 0; mi < 4; mi++)
#pragma unroll
                for (int p = 0; p < 2; p++){
                    mma16(acc[mi][2*p],   af[mi], bf[p][0], bf[p][2]);
                    mma16(acc[mi][2*p+1], af[mi], bf[p][1], bf[p][3]);
                }
        }
        __syncthreads();
        if (kt + 2 < nk) stage(kt + 2, s);
    }

    // epilogue
#pragma unroll
    for (int mi = 0; mi < 4; mi++){
#pragma unroll
        for (int t = 0; t < 4; t++){
            int col  = bn + wn + t*8 + 2*tg;
            int row0 = bm + wm + mi*16 + g;
            if (out_half){
                __half2 h0 = __floats2half2_rn(acc[mi][t][0], acc[mi][t][1]);
                __half2 h1 = __floats2half2_rn(acc[mi][t][2], acc[mi][t][3]);
                *(__half2*)((__half*)C + (size_t)row0      *EMB + col) = h0;
                *(__half2*)((__half*)C + (size_t)(row0 + 8)*EMB + col) = h1;
            } else {
                float b0 = bias ? bias[col]   : 0.f;
                float b1 = bias ? bias[col+1] : 0.f;
                float2 v0 = make_float2(acc[mi][t][0] + b0, acc[mi][t][1] + b1);
                float2 v1 = make_float2(acc[mi][t][2] + b0, acc[mi][t][3] + b1);
                *(float2*)((float*)C + (size_t)row0      *EMB + col) = v0;
                *(float2*)((float*)C + (size_t)(row0 + 8)*EMB + col) = v1;
            }
        }
    }
}

__global__ void __launch_bounds__(256, 2) gemm_qkv(
    const __half* __restrict__ x,
    const __half* __restrict__ Wq, const __half* __restrict__ Wk,
    const __half* __restrict__ Wv,
    __half* __restrict__ q, __half* __restrict__ k, __half* __restrict__ v)
{
    const __half* W = (blockIdx.z == 0) ? Wq : (blockIdx.z == 1) ? Wk : Wv;
    __half*       C = (blockIdx.z == 0) ? q  : (blockIdx.z == 1) ? k  : v;
    gemm_body(x, W, nullptr, C, 1);
}
__global__ void __launch_bounds__(256, 2) gemm_out(
    const __half* __restrict__ A, const __half* __restrict__ W,
    const float* __restrict__ bias, float* __restrict__ C)
{
    gemm_body(A, W, bias, C, 0);
}

// ------------------------------------------------------------------
// Flash attention v2 (causal), fp16 operands / fp32 softmax+accum.
// grid(16, B*H), 256 threads (8 warps), q-tile 128, 16 q-rows/warp.
// Softmax: mask+max in RAW score domain, scale max once (cs>0), fuse
// scale+subtract into fmaf before ex2 (saves FMUL+FADD per element).
// K/V double-buffered cp.async prefetch; PV B-frags via ldmatrix.trans.
// ------------------------------------------------------------------
#define QS_B (128*RS)      // 18432
#define KS_B (64*RS)       //  9216
#define ATTN_SMEM (QS_B + 4*KS_B)   // 55296

__global__ void __launch_bounds__(256, 2) attn_kernel(
    const __half* __restrict__ Q, const __half* __restrict__ K,
    const __half* __restrict__ V, __half* __restrict__ O)
{
    extern __shared__ uint32_t dyn[];
    const uint32_t sbase = (uint32_t)__cvta_generic_to_shared(dyn);
    const uint32_t qsa = sbase;

    const int tid  = threadIdx.x;
    const int lane = tid & 31, g = lane >> 2, tg = lane & 3;
    const int wq   = tid >> 5;                      // 0..7, 16 q rows each
    const int qt   = gridDim.x - 1 - blockIdx.x;    // heavy blocks first
    const int b    = blockIdx.y >> 4;
    const int h    = blockIdx.y & 15;
    const int qbase = qt * 128;
    const float cs = 0.125f * 1.44269504088896f;    // 1/sqrt(64)*log2(e)

    const int alr = lane & 15, alk = (lane >> 4) * 16;

    const __half* Qg = Q + (size_t)(b*SEQ + qbase)*EMB + h*64;
    const __half* Kg = K + (size_t)(b*SEQ)*EMB + h*64;
    const __half* Vg = V + (size_t)(b*SEQ)*EMB + h*64;

    auto kbuf = [&](int s){ return sbase + QS_B + (uint32_t)s*KS_B; };
    auto vbuf = [&](int s){ return sbase + QS_B + 2*KS_B + (uint32_t)s*KS_B; };

    auto load_kv = [&](int jt, int s){
        uint32_t ka = kbuf(s), va = vbuf(s);
#pragma unroll
        for (int i = 0; i < 2; i++){
            int id = tid + i*256, r = id >> 3, c = id & 7;
            cpa16(ka + r*RS + c*16, Kg + (size_t)(jt*64 + r)*EMB + c*8);
        }
#pragma unroll
        for (int i = 0; i < 2; i++){
            int id = tid + i*256, r = id >> 3, c = id & 7;
            cpa16(va + r*RS + c*16, Vg + (size_t)(jt*64 + r)*EMB + c*8);
        }
    };

    // prologue: Q + tile 0 as one group
#pragma unroll
    for (int i = 0; i < 4; i++){
        int id = tid + i*256, r = id >> 3, c = id & 7;
        cpa16(qsa + r*RS + c*16, Qg + (size_t)r*EMB + c*8);
    }
    load_kv(0, 0);
    cpa_commit();

    float m0 = -1e30f, m1 = -1e30f, l0 = 0.f, l1 = 0.f;
    float o[8][4];
#pragma unroll
    for (int t = 0; t < 8; t++)
#pragma unroll
        for (int j = 0; j < 4; j++) o[t][j] = 0.f;

    const int q0r = qbase + wq*16 + g;     // this thread's 2 q rows
    const int q1r = q0r + 8;

    const int njt = 2*qt + 2;
    for (int jt = 0; jt < njt; jt++){
        const int s = jt & 1;
        __syncthreads();                 // all warps done with buffer s^1
        if (jt + 1 < njt){
            load_kv(jt + 1, s ^ 1);
            cpa_commit();
            cpa_wait1();                 // tile jt arrived (jt+1 in flight)
        } else {
            cpa_wait0();
        }
        __syncthreads();                 // tile jt visible to all warps

        const uint32_t ka = kbuf(s), va = vbuf(s);

        // ---- S = Q @ K^T : 16 q-rows x 64 keys per warp (raw scores)
        float sacc[8][4];
#pragma unroll
        for (int t = 0; t < 8; t++)
#pragma unroll
            for (int j = 0; j < 4; j++) sacc[t][j] = 0.f;
#pragma unroll
        for (int ks = 0; ks < 4; ks++){        // 4 x k16 over d
            uint32_t aq[4], bk[4][4];
            ldsm4(aq, qsa + (wq*16 + alr)*RS + ks*32 + alk);
#pragma unroll
            for (int p = 0; p < 4; p++)
                ldsm4(bk[p], ka + (p*16 + alr)*RS + ks*32 + alk);
#pragma unroll
            for (int p = 0; p < 4; p++){
                mma16(sacc[2*p],   aq, bk[p][0], bk[p][2]);
                mma16(sacc[2*p+1], aq, bk[p][1], bk[p][3]);
            }
        }

        // ---- causal mask (raw) + online softmax (max in raw domain)
        const bool need_mask = (jt >= 2*qt);
        {
            float tm0 = -1e30f, tm1 = -1e30f;
#pragma unroll
            for (int t = 0; t < 8; t++){
                float* sc = sacc[t];
                if (need_mask){
                    int jc = jt*64 + t*8 + 2*tg;
                    if (jc     > q0r) sc[0] = -1e30f;
                    if (jc + 1 > q0r) sc[1] = -1e30f;
                    if (jc     > q1r) sc[2] = -1e30f;
                    if (jc + 1 > q1r) sc[3] = -1e30f;
                }
                tm0 = fmaxf(tm0, fmaxf(sc[0], sc[1]));
                tm1 = fmaxf(tm1, fmaxf(sc[2], sc[3]));
            }
            tm0 = fmaxf(tm0, __shfl_xor_sync(0xffffffffu, tm0, 1));
            tm0 = fmaxf(tm0, __shfl_xor_sync(0xffffffffu, tm0, 2));
            tm1 = fmaxf(tm1, __shfl_xor_sync(0xffffffffu, tm1, 1));
            tm1 = fmaxf(tm1, __shfl_xor_sync(0xffffffffu, tm1, 2));
            float mn0 = fmaxf(m0, tm0 * cs);
            float mn1 = fmaxf(m1, tm1 * cs);
            float a0  = ex2f(m0 - mn0);
            float a1  = ex2f(m1 - mn1);
            float rs0 = 0.f, rs1 = 0.f;
#pragma unroll
            for (int t = 0; t < 8; t++){
                float* sc = sacc[t];
                sc[0] = ex2f(fmaf(sc[0], cs, -mn0));
                sc[1] = ex2f(fmaf(sc[1], cs, -mn0));
                sc[2] = ex2f(fmaf(sc[2], cs, -mn1));
                sc[3] = ex2f(fmaf(sc[3], cs, -mn1));
                rs0 += sc[0] + sc[1];
                rs1 += sc[2] + sc[3];
            }
            rs0 += __shfl_xor_sync(0xffffffffu, rs0, 1);
            rs0 += __shfl_xor_sync(0xffffffffu, rs0, 2);
            rs1 += __shfl_xor_sync(0xffffffffu, rs1, 1);
            rs1 += __shfl_xor_sync(0xffffffffu, rs1, 2);
            l0 = l0*a0 + rs0;
            l1 = l1*a1 + rs1;
            m0 = mn0; m1 = mn1;
#pragma unroll
            for (int t = 0; t < 8; t++){
                o[t][0] *= a0; o[t][1] *= a0;
                o[t][2] *= a1; o[t][3] *= a1;
            }
        }

        // ---- O += P @ V : B-frags via ldmatrix.trans on row-major V
#pragma unroll
        for (int ks = 0; ks < 4; ks++){        // 4 x k16 over keys
            uint32_t av[4];                    // A-frag from S C-frags
            av[0] = ph2(sacc[2*ks][0],   sacc[2*ks][1]);
            av[1] = ph2(sacc[2*ks][2],   sacc[2*ks][3]);
            av[2] = ph2(sacc[2*ks+1][0], sacc[2*ks+1][1]);
            av[3] = ph2(sacc[2*ks+1][2], sacc[2*ks+1][3]);
#pragma unroll
            for (int p = 0; p < 4; p++){       // d pairs of 16
                uint32_t bv[4];
                ldsm4t(bv, va + (ks*16 + alr)*RS + p*32 + alk);
                mma16(o[2*p],   av, bv[0], bv[1]);
                mma16(o[2*p+1], av, bv[2], bv[3]);
            }
        }
    }

    // ---- epilogue: normalize, store half (feeds final GEMM)
    {
        float i0 = 1.f / l0;
        float i1 = 1.f / l1;
        size_t r0 = (size_t)(b*SEQ + q0r);
#pragma unroll
        for (int t = 0; t < 8; t++){
            int col = h*64 + t*8 + 2*tg;
            __half2 h0 = __floats2half2_rn(o[t][0]*i0, o[t][1]*i0);
            __half2 h1 = __floats2half2_rn(o[t][2]*i1, o[t][3]*i1);
            *(__half2*)(O + r0*EMB + col)       = h0;
            *(__half2*)(O + (r0 + 8)*EMB + col) = h1;
        }
    }
}

// ------------------------------------------------------------------
extern "C" void kernel_launch(void* const* d_in, const int* in_sizes, int n_in,
                              void* d_out, int out_size)
{
    const float* x  = (const float*)d_in[0];
    const float* Wq = (const float*)d_in[1];
    const float* Wk = (const float*)d_in[2];
    const float* Wv = (const float*)d_in[3];
    const float* Wo = (const float*)d_in[4];
    const float* bo = (const float*)d_in[5];
    float* out = (float*)d_out;

    __half *q, *k, *v, *ao, *xc, *wq, *wk, *wv, *wo;
    cudaGetSymbolAddress((void**)&q,  g_q);
    cudaGetSymbolAddress((void**)&k,  g_k);
    cudaGetSymbolAddress((void**)&v,  g_v);
    cudaGetSymbolAddress((void**)&ao, g_ao);
    cudaGetSymbolAddress((void**)&xc, g_xc);
    cudaGetSymbolAddress((void**)&wq, g_wq);
    cudaGetSymbolAddress((void**)&wk, g_wk);
    cudaGetSymbolAddress((void**)&wv, g_wv);
    cudaGetSymbolAddress((void**)&wo, g_wo);

    cudaFuncSetAttribute(gemm_qkv,
                         cudaFuncAttributeMaxDynamicSharedMemorySize, GEMM_SMEM);
    cudaFuncSetAttribute(gemm_out,
                         cudaFuncAttributeMaxDynamicSharedMemorySize, GEMM_SMEM);
    cudaFuncSetAttribute(attn_kernel,
                         cudaFuncAttributeMaxDynamicSharedMemorySize, ATTN_SMEM);

    // pre-round inputs to fp16
    const int nx4 = MR*EMB/4, nw4 = EMB*EMB/4;
    cvt_f2h<<<(nx4+255)/256, 256>>>((const float4*)x, (uint2*)xc, nx4);
    dim3 gw((nw4+255)/256, 4);
    cvt_f2h4<<<gw, 256>>>((const float4*)Wq, (const float4*)Wk,
                          (const float4*)Wv, (const float4*)Wo,
                          (uint2*)wq, (uint2*)wk, (uint2*)wv, (uint2*)wo, nw4);

    dim3 gq(EMB/128, MR/128, 3);          // 8 x 64 x 3
    gemm_qkv<<<gq, 256, GEMM_SMEM>>>(xc, wq, wk, wv, q, k, v);

    dim3 ga(SEQ/128, NB*NH);              // 16 x 64
    attn_kernel<<<ga, 256, ATTN_SMEM>>>(q, k, v, ao);

    dim3 go(EMB/128, MR/128);             // 8 x 64
    gemm_out<<<go, 256, GEMM_SMEM>>>(ao, wo, bo, out);
}

// round 13
// speedup vs baseline: 2.8463x; 1.0308x over previous
#include <cuda_runtime.h>
#include <cuda_fp16.h>
#include <cstdint>
#include <cstddef>

#define EMB 1024
#define SEQ 2048
#define NB  4
#define NH  16
#define MR  (NB*SEQ)   // 8192 rows

// static device scratch (allocation-guard safe) — fp16 activations/weights
__device__ __half g_q [(size_t)MR*EMB];
__device__ __half g_k [(size_t)MR*EMB];
__device__ __half g_v [(size_t)MR*EMB];
__device__ __half g_ao[(size_t)MR*EMB];
__device__ __half g_xc[(size_t)MR*EMB];
__device__ __half g_wq[(size_t)EMB*EMB];
__device__ __half g_wk[(size_t)EMB*EMB];
__device__ __half g_wv[(size_t)EMB*EMB];
__device__ __half g_wo[(size_t)EMB*EMB];

__device__ __forceinline__ float ex2f(float x){
    float y; asm("ex2.approx.ftz.f32 %0, %1;" : "=f"(y) : "f"(x)); return y;
}
// D += A*B : m16n8k16 fp16 in / fp32 accum.
// A frag: a0=(g,2tg..) a1=(g+8,2tg..) a2=(g,2tg+8..) a3=(g+8,2tg+8..)
// B frag: b0=(k=2tg..,n=g) b1=(k=2tg+8..,n=g)
// C frag: c0=(g,2tg) c1=(g,2tg+1) c2=(g+8,2tg) c3=(g+8,2tg+1)
__device__ __forceinline__ void mma16(float* d, const uint32_t* a,
                                      uint32_t b0, uint32_t b1){
    asm volatile(
      "mma.sync.aligned.m16n8k16.row.col.f32.f16.f16.f32 "
      "{%0,%1,%2,%3}, {%4,%5,%6,%7}, {%8,%9}, {%0,%1,%2,%3};\n"
      : "+f"(d[0]), "+f"(d[1]), "+f"(d[2]), "+f"(d[3])
      : "r"(a[0]), "r"(a[1]), "r"(a[2]), "r"(a[3]), "r"(b0), "r"(b1));
}
__device__ __forceinline__ void ldsm4(uint32_t* r, uint32_t saddr){
    asm volatile("ldmatrix.sync.aligned.m8n8.x4.shared.b16 {%0,%1,%2,%3}, [%4];"
        : "=r"(r[0]), "=r"(r[1]), "=r"(r[2]), "=r"(r[3]) : "r"(saddr));
}
__device__ __forceinline__ void ldsm4t(uint32_t* r, uint32_t saddr){
    asm volatile("ldmatrix.sync.aligned.m8n8.x4.trans.shared.b16 {%0,%1,%2,%3}, [%4];"
        : "=r"(r[0]), "=r"(r[1]), "=r"(r[2]), "=r"(r[3]) : "r"(saddr));
}
__device__ __forceinline__ void cpa16(uint32_t saddr, const void* g){
    asm volatile("cp.async.ca.shared.global [%0], [%1], 16;" :: "r"(saddr), "l"(g));
}
__device__ __forceinline__ void cpa_commit(){ asm volatile("cp.async.commit_group;"); }
__device__ __forceinline__ void cpa_wait0(){ asm volatile("cp.async.wait_group 0;"); }
__device__ __forceinline__ void cpa_wait1(){ asm volatile("cp.async.wait_group 1;"); }
__device__ __forceinline__ uint32_t ph2(float lo, float hi){
    __half2 t = __floats2half2_rn(lo, hi);
    return *(uint32_t*)&t;
}

// ------------------------------------------------------------------
// Fused fp32 -> fp16 pre-round: one launch for x + 4 weights.
// 12 chunks of 262144 float4 on blockIdx.y (x = 8 chunks, weights 1 each).
// Each thread converts 2 independent float4s (ILP 2).
// ------------------------------------------------------------------
#define CVT_CH 262144   // float4 per chunk (= 1M floats)

__global__ void __launch_bounds__(256) cvt_all(
    const float4* __restrict__ x,
    const float4* __restrict__ Wq, const float4* __restrict__ Wk,
    const float4* __restrict__ Wv, const float4* __restrict__ Wo,
    uint2* __restrict__ xc,
    uint2* __restrict__ wq, uint2* __restrict__ wk,
    uint2* __restrict__ wv, uint2* __restrict__ wo)
{
    const int c = blockIdx.y;
    const float4* s; uint2* d;
    if (c < 8){ s = x + (size_t)c*CVT_CH; d = xc + (size_t)c*CVT_CH; }
    else if (c == 8){ s = Wq; d = wq; }
    else if (c == 9){ s = Wk; d = wk; }
    else if (c == 10){ s = Wv; d = wv; }
    else { s = Wo; d = wo; }

    int i0 = blockIdx.x*256 + threadIdx.x;     // [0, 131072)
    int i1 = i0 + CVT_CH/2;                    // [131072, 262144)
    float4 v0 = s[i0];
    float4 v1 = s[i1];
    uint2 o0, o1;
    o0.x = ph2(v0.x, v0.y); o0.y = ph2(v0.z, v0.w);
    o1.x = ph2(v1.x, v1.y); o1.y = ph2(v1.z, v1.w);
    d[i0] = o0;
    d[i1] = o1;
}

// ------------------------------------------------------------------
// fp16 GEMM (R12-proven, unchanged): C[M,N] = A[M,K] @ W[N,K]^T (+bias).
// Block 128(m) x 128(n), BK=64 halves, 256 thr, warps 2(m)x4(n) -> 64x32.
// __launch_bounds__(256,2) -> 2 CTAs/SM. cp.async double-buffered.
// ------------------------------------------------------------------
#define RS   144                              // row stride bytes
#define GT_B (128*RS)                         // 18432 per operand tile
#define GSTG (2*GT_B)                         // 36864
#define GEMM_SMEM (2*GSTG)                    // 73728

__device__ __forceinline__ void gemm_body(
    const __half* __restrict__ A, const __half* __restrict__ W,
    const float* __restrict__ bias, void* __restrict__ C, int out_half)
{
    extern __shared__ uint32_t sh[];
    const uint32_t sbase = (uint32_t)__cvta_generic_to_shared(sh);

    const int tid  = threadIdx.x;
    const int lane = tid & 31, g = lane >> 2, tg = lane & 3;
    const int wid  = tid >> 5;
    const int wm   = (wid & 1) * 64;
    const int wn   = (wid >> 1) * 32;
    const int bm   = blockIdx.y * 128;
    const int bn   = blockIdx.x * 128;

    const int alr = lane & 15;
    const int alk = (lane >> 4) * 16;

    const __half* Ag = A + (size_t)bm*EMB;
    const __half* Wg = W + (size_t)bn*EMB;

    float acc[4][4][4];
#pragma unroll
    for (int mi = 0; mi < 4; mi++)
#pragma unroll
        for (int t = 0; t < 4; t++)
#pragma unroll
            for (int j = 0; j < 4; j++) acc[mi][t][j] = 0.f;

    auto stage = [&](int kt, int s){
        const uint32_t sa = sbase + (uint32_t)s*GSTG;
        const uint32_t sb = sa + GT_B;
#pragma unroll
        for (int i = 0; i < 4; i++){
            int id = tid + i*256, r = id >> 3, c = id & 7;
            cpa16(sa + r*RS + c*16, Ag + (size_t)r*EMB + kt*64 + c*8);
        }
#pragma unroll
        for (int i = 0; i < 4; i++){
            int id = tid + i*256, r = id >> 3, c = id & 7;
            cpa16(sb + r*RS + c*16, Wg + (size_t)r*EMB + kt*64 + c*8);
        }
        cpa_commit();
    };

    stage(0, 0);
    stage(1, 1);

    const int nk = EMB/64;   // 16
    for (int kt = 0; kt < nk; kt++){
        const int s = kt & 1;
        if (kt + 1 < nk) cpa_wait1(); else cpa_wait0();
        __syncthreads();
        const uint32_t sa = sbase + (uint32_t)s*GSTG;
        const uint32_t sb = sa + GT_B;
#pragma unroll
        for (int kk = 0; kk < 4; kk++){        // 4 x k16
            uint32_t af[4][4], bf[2][4];
#pragma unroll
            for (int mi = 0; mi < 4; mi++)
                ldsm4(af[mi], sa + (wm + mi*16 + alr)*RS + kk*32 + alk);
#pragma unroll
            for (int p = 0; p < 2; p++)
                ldsm4(bf[p], sb + (wn + p*16 + alr)*RS + kk*32 + alk);
#pragma unroll
            for (int mi = 0; mi < 4; mi++)
#pragma unroll
                for (int p = 0; p < 2; p++){
                    mma16(acc[mi][2*p],   af[mi], bf[p][0], bf[p][2]);
                    mma16(acc[mi][2*p+1], af[mi], bf[p][1], bf[p][3]);
                }
        }
        __syncthreads();
        if (kt + 2 < nk) stage(kt + 2, s);
    }

    // epilogue
#pragma unroll
    for (int mi = 0; mi < 4; mi++){
#pragma unroll
        for (int t = 0; t < 4; t++){
            int col  = bn + wn + t*8 + 2*tg;
            int row0 = bm + wm + mi*16 + g;
            if (out_half){
                __half2 h0 = __floats2half2_rn(acc[mi][t][0], acc[mi][t][1]);
                __half2 h1 = __floats2half2_rn(acc[mi][t][2], acc[mi][t][3]);
                *(__half2*)((__half*)C + (size_t)row0      *EMB + col) = h0;
                *(__half2*)((__half*)C + (size_t)(row0 + 8)*EMB + col) = h1;
            } else {
                float b0 = bias ? bias[col]   : 0.f;
                float b1 = bias ? bias[col+1] : 0.f;
                float2 v0 = make_float2(acc[mi][t][0] + b0, acc[mi][t][1] + b1);
                float2 v1 = make_float2(acc[mi][t][2] + b0, acc[mi][t][3] + b1);
                *(float2*)((float*)C + (size_t)row0      *EMB + col) = v0;
                *(float2*)((float*)C + (size_t)(row0 + 8)*EMB + col) = v1;
            }
        }
    }
}

__global__ void __launch_bounds__(256, 2) gemm_qkv(
    const __half* __restrict__ x,
    const __half* __restrict__ Wq, const __half* __restrict__ Wk,
    const __half* __restrict__ Wv,
    __half* __restrict__ q, __half* __restrict__ k, __half* __restrict__ v)
{
    const __half* W = (blockIdx.z == 0) ? Wq : (blockIdx.z == 1) ? Wk : Wv;
    __half*       C = (blockIdx.z == 0) ? q  : (blockIdx.z == 1) ? k  : v;
    gemm_body(x, W, nullptr, C, 1);
}
__global__ void __launch_bounds__(256, 2) gemm_out(
    const __half* __restrict__ A, const __half* __restrict__ W,
    const float* __restrict__ bias, float* __restrict__ C)
{
    gemm_body(A, W, bias, C, 0);
}

// ------------------------------------------------------------------
// Flash attention v2 (causal), fp16 operands / fp32 softmax+accum.
// grid(16, B*H), 256 threads (8 warps), q-tile 128, 16 q-rows/warp.
// Q fragments HOISTED to registers (loaded once, loop touches only K/V).
// K/V double-buffered cp.async prefetch; PV B-frags via ldmatrix.trans.
// Softmax: mask+max in raw domain, fused scale+subtract via fmaf.
// ------------------------------------------------------------------
#define QS_B (128*RS)      // 18432
#define KS_B (64*RS)       //  9216
#define ATTN_SMEM (QS_B + 4*KS_B)   // 55296

__global__ void __launch_bounds__(256, 2) attn_kernel(
    const __half* __restrict__ Q, const __half* __restrict__ K,
    const __half* __restrict__ V, __half* __restrict__ O)
{
    extern __shared__ uint32_t dyn[];
    const uint32_t sbase = (uint32_t)__cvta_generic_to_shared(dyn);
    const uint32_t qsa = sbase;

    const int tid  = threadIdx.x;
    const int lane = tid & 31, g = lane >> 2, tg = lane & 3;
    const int wq   = tid >> 5;                      // 0..7, 16 q rows each
    const int qt   = gridDim.x - 1 - blockIdx.x;    // heavy blocks first
    const int b    = blockIdx.y >> 4;
    const int h    = blockIdx.y & 15;
    const int qbase = qt * 128;
    const float cs = 0.125f * 1.44269504088896f;    // 1/sqrt(64)*log2(e)

    const int alr = lane & 15, alk = (lane >> 4) * 16;

    const __half* Qg = Q + (size_t)(b*SEQ + qbase)*EMB + h*64;
    const __half* Kg = K + (size_t)(b*SEQ)*EMB + h*64;
    const __half* Vg = V + (size_t)(b*SEQ)*EMB + h*64;

    auto kbuf = [&](int s){ return sbase + QS_B + (uint32_t)s*KS_B; };
    auto vbuf = [&](int s){ return sbase + QS_B + 2*KS_B + (uint32_t)s*KS_B; };

    auto load_kv = [&](int jt, int s){
        uint32_t ka = kbuf(s), va = vbuf(s);
#pragma unroll
        for (int i = 0; i < 2; i++){
            int id = tid + i*256, r = id >> 3, c = id & 7;
            cpa16(ka + r*RS + c*16, Kg + (size_t)(jt*64 + r)*EMB + c*8);
        }
#pragma unroll
        for (int i = 0; i < 2; i++){
            int id = tid + i*256, r = id >> 3, c = id & 7;
            cpa16(va + r*RS + c*16, Vg + (size_t)(jt*64 + r)*EMB + c*8);
        }
    };

    const int njt = 2*qt + 2;     // always >= 2

    // prologue: group0 = Q + kv0 ; group1 = kv1 ; retire group0, load qf
#pragma unroll
    for (int i = 0; i < 4; i++){
        int id = tid + i*256, r = id >> 3, c = id & 7;
        cpa16(qsa + r*RS + c*16, Qg + (size_t)r*EMB + c*8);
    }
    load_kv(0, 0);
    cpa_commit();
    load_kv(1, 1);
    cpa_commit();
    cpa_wait1();                 // Q + kv0 arrived (kv1 in flight)
    __syncthreads();

    uint32_t qf[4][4];           // Q A-frags, loop-invariant
#pragma unroll
    for (int ks = 0; ks < 4; ks++)
        ldsm4(qf[ks], qsa + (wq*16 + alr)*RS + ks*32 + alk);

    float m0 = -1e30f, m1 = -1e30f, l0 = 0.f, l1 = 0.f;
    float o[8][4];
#pragma unroll
    for (int t = 0; t < 8; t++)
#pragma unroll
        for (int j = 0; j < 4; j++) o[t][j] = 0.f;

    const int q0r = qbase + wq*16 + g;     // this thread's 2 q rows
    const int q1r = q0r + 8;

    for (int jt = 0; jt < njt; jt++){
        const int s = jt & 1;
        // invariant: tile jt arrived and visible; tile jt+1 (if any) in flight
        const uint32_t ka = kbuf(s), va = vbuf(s);

        // ---- S = Q @ K^T : 16 q-rows x 64 keys per warp (raw scores)
        float sacc[8][4];
#pragma unroll
        for (int t = 0; t < 8; t++)
#pragma unroll
            for (int j = 0; j < 4; j++) sacc[t][j] = 0.f;
#pragma unroll
        for (int ks = 0; ks < 4; ks++){        // 4 x k16 over d
            uint32_t bk[4][4];
#pragma unroll
            for (int p = 0; p < 4; p++)
                ldsm4(bk[p], ka + (p*16 + alr)*RS + ks*32 + alk);
#pragma unroll
            for (int p = 0; p < 4; p++){
                mma16(sacc[2*p],   qf[ks], bk[p][0], bk[p][2]);
                mma16(sacc[2*p+1], qf[ks], bk[p][1], bk[p][3]);
            }
        }

        // ---- causal mask (raw) + online softmax (max in raw domain)
        const bool need_mask = (jt >= 2*qt);
        {
            float tm0 = -1e30f, tm1 = -1e30f;
#pragma unroll
            for (int t = 0; t < 8; t++){
                float* sc = sacc[t];
                if (need_mask){
                    int jc = jt*64 + t*8 + 2*tg;
                    if (jc     > q0r) sc[0] = -1e30f;
                    if (jc + 1 > q0r) sc[1] = -1e30f;
                    if (jc     > q1r) sc[2] = -1e30f;
                    if (jc + 1 > q1r) sc[3] = -1e30f;
                }
                tm0 = fmaxf(tm0, fmaxf(sc[0], sc[1]));
                tm1 = fmaxf(tm1, fmaxf(sc[2], sc[3]));
            }
            tm0 = fmaxf(tm0, __shfl_xor_sync(0xffffffffu, tm0, 1));
            tm0 = fmaxf(tm0, __shfl_xor_sync(0xffffffffu, tm0, 2));
            tm1 = fmaxf(tm1, __shfl_xor_sync(0xffffffffu, tm1, 1));
            tm1 = fmaxf(tm1, __shfl_xor_sync(0xffffffffu, tm1, 2));
            float mn0 = fmaxf(m0, tm0 * cs);
            float mn1 = fmaxf(m1, tm1 * cs);
            float a0  = ex2f(m0 - mn0);
            float a1  = ex2f(m1 - mn1);
            float rs0 = 0.f, rs1 = 0.f;
#pragma unroll
            for (int t = 0; t < 8; t++){
                float* sc = sacc[t];
                sc[0] = ex2f(fmaf(sc[0], cs, -mn0));
                sc[1] = ex2f(fmaf(sc[1], cs, -mn0));
                sc[2] = ex2f(fmaf(sc[2], cs, -mn1));
                sc[3] = ex2f(fmaf(sc[3], cs, -mn1));
                rs0 += sc[0] + sc[1];
                rs1 += sc[2] + sc[3];
            }
            rs0 += __shfl_xor_sync(0xffffffffu, rs0, 1);
            rs0 += __shfl_xor_sync(0xffffffffu, rs0, 2);
            rs1 += __shfl_xor_sync(0xffffffffu, rs1, 1);
            rs1 += __shfl_xor_sync(0xffffffffu, rs1, 2);
            l0 = l0*a0 + rs0;
            l1 = l1*a1 + rs1;
            m0 = mn0; m1 = mn1;
#pragma unroll
            for (int t = 0; t < 8; t++){
                o[t][0] *= a0; o[t][1] *= a0;
                o[t][2] *= a1; o[t][3] *= a1;
            }
        }

        // ---- O += P @ V : B-frags via ldmatrix.trans on row-major V
#pragma unroll
        for (int ks = 0; ks < 4; ks++){        // 4 x k16 over keys
            uint32_t av[4];                    // A-frag from S C-frags
            av[0] = ph2(sacc[2*ks][0],   sacc[2*ks][1]);
            av[1] = ph2(sacc[2*ks][2],   sacc[2*ks][3]);
            av[2] = ph2(sacc[2*ks+1][0], sacc[2*ks+1][1]);
            av[3] = ph2(sacc[2*ks+1][2], sacc[2*ks+1][3]);
#pragma unroll
            for (int p = 0; p < 4; p++){       // d pairs of 16
                uint32_t bv[4];
                ldsm4t(bv, va + (ks*16 + alr)*RS + p*32 + alk);
                mma16(o[2*p],   av, bv[0], bv[1]);
                mma16(o[2*p+1], av, bv[2], bv[3]);
            }
        }

        // ---- pipeline: free buffer s, prefetch jt+2, ensure jt+1 arrived
        __syncthreads();                       // all warps done with buffer s
        if (jt + 1 < njt){
            if (jt + 2 < njt){ load_kv(jt + 2, s); cpa_commit(); cpa_wait1(); }
            else             { cpa_wait0(); }
            __syncthreads();                   // tile jt+1 visible to all
        }
    }

    // ---- epilogue: normalize, store half (feeds final GEMM)
    {
        float i0 = 1.f / l0;
        float i1 = 1.f / l1;
        size_t r0 = (size_t)(b*SEQ + q0r);
#pragma unroll
        for (int t = 0; t < 8; t++){
            int col = h*64 + t*8 + 2*tg;
            __half2 h0 = __floats2half2_rn(o[t][0]*i0, o[t][1]*i0);
            __half2 h1 = __floats2half2_rn(o[t][2]*i1, o[t][3]*i1);
            *(__half2*)(O + r0*EMB + col)       = h0;
            *(__half2*)(O + (r0 + 8)*EMB + col) = h1;
        }
    }
}

// ------------------------------------------------------------------
extern "C" void kernel_launch(void* const* d_in, const int* in_sizes, int n_in,
                              void* d_out, int out_size)
{
    const float* x  = (const float*)d_in[0];
    const float* Wq = (const float*)d_in[1];
    const float* Wk = (const float*)d_in[2];
    const float* Wv = (const float*)d_in[3];
    const float* Wo = (const float*)d_in[4];
    const float* bo = (const float*)d_in[5];
    float* out = (float*)d_out;

    __half *q, *k, *v, *ao, *xc, *wq, *wk, *wv, *wo;
    cudaGetSymbolAddress((void**)&q,  g_q);
    cudaGetSymbolAddress((void**)&k,  g_k);
    cudaGetSymbolAddress((void**)&v,  g_v);
    cudaGetSymbolAddress((void**)&ao, g_ao);
    cudaGetSymbolAddress((void**)&xc, g_xc);
    cudaGetSymbolAddress((void**)&wq, g_wq);
    cudaGetSymbolAddress((void**)&wk, g_wk);
    cudaGetSymbolAddress((void**)&wv, g_wv);
    cudaGetSymbolAddress((void**)&wo, g_wo);

    cudaFuncSetAttribute(gemm_qkv,
                         cudaFuncAttributeMaxDynamicSharedMemorySize, GEMM_SMEM);
    cudaFuncSetAttribute(gemm_out,
                         cudaFuncAttributeMaxDynamicSharedMemorySize, GEMM_SMEM);
    cudaFuncSetAttribute(attn_kernel,
                         cudaFuncAttributeMaxDynamicSharedMemorySize, ATTN_SMEM);

    // fused fp32->fp16 pre-round (x: 8 chunks, weights: 1 chunk each)
    dim3 gc(CVT_CH/(256*2), 12);          // 512 x 12
    cvt_all<<<gc, 256>>>((const float4*)x,
                         (const float4*)Wq, (const float4*)Wk,
                         (const float4*)Wv, (const float4*)Wo,
                         (uint2*)xc, (uint2*)wq, (uint2*)wk,
                         (uint2*)wv, (uint2*)wo);

    dim3 gq(EMB/128, MR/128, 3);          // 8 x 64 x 3
    gemm_qkv<<<gq, 256, GEMM_SMEM>>>(xc, wq, wk, wv, q, k, v);

    dim3 ga(SEQ/128, NB*NH);              // 16 x 64
    attn_kernel<<<ga, 256, ATTN_SMEM>>>(q, k, v, ao);

    dim3 go(EMB/128, MR/128);             // 8 x 64
    gemm_out<<<go, 256, GEMM_SMEM>>>(ao, wo, bo, out);
}

// round 14
// speedup vs baseline: 2.8903x; 1.0155x over previous
#include <cuda_runtime.h>
#include <cuda_fp16.h>
#include <cstdint>
#include <cstddef>

#define EMB 1024
#define SEQ 2048
#define NB  4
#define NH  16
#define MR  (NB*SEQ)   // 8192 rows

// static device scratch (allocation-guard safe) — fp16 activations/weights
__device__ __half g_q [(size_t)MR*EMB];
__device__ __half g_k [(size_t)MR*EMB];
__device__ __half g_v [(size_t)MR*EMB];
__device__ __half g_ao[(size_t)MR*EMB];
__device__ __half g_xc[(size_t)MR*EMB];
__device__ __half g_wq[(size_t)EMB*EMB];
__device__ __half g_wk[(size_t)EMB*EMB];
__device__ __half g_wv[(size_t)EMB*EMB];
__device__ __half g_wo[(size_t)EMB*EMB];

__device__ __forceinline__ float ex2f(float x){
    float y; asm("ex2.approx.ftz.f32 %0, %1;" : "=f"(y) : "f"(x)); return y;
}
// D += A*B : m16n8k16 fp16 in / fp32 accum.
// A frag: a0=(g,2tg..) a1=(g+8,2tg..) a2=(g,2tg+8..) a3=(g+8,2tg+8..)
// B frag: b0=(k=2tg..,n=g) b1=(k=2tg+8..,n=g)
// C frag: c0=(g,2tg) c1=(g,2tg+1) c2=(g+8,2tg) c3=(g+8,2tg+1)
__device__ __forceinline__ void mma16(float* d, const uint32_t* a,
                                      uint32_t b0, uint32_t b1){
    asm volatile(
      "mma.sync.aligned.m16n8k16.row.col.f32.f16.f16.f32 "
      "{%0,%1,%2,%3}, {%4,%5,%6,%7}, {%8,%9}, {%0,%1,%2,%3};\n"
      : "+f"(d[0]), "+f"(d[1]), "+f"(d[2]), "+f"(d[3])
      : "r"(a[0]), "r"(a[1]), "r"(a[2]), "r"(a[3]), "r"(b0), "r"(b1));
}
__device__ __forceinline__ void ldsm4(uint32_t* r, uint32_t saddr){
    asm volatile("ldmatrix.sync.aligned.m8n8.x4.shared.b16 {%0,%1,%2,%3}, [%4];"
        : "=r"(r[0]), "=r"(r[1]), "=r"(r[2]), "=r"(r[3]) : "r"(saddr));
}
__device__ __forceinline__ void ldsm4t(uint32_t* r, uint32_t saddr){
    asm volatile("ldmatrix.sync.aligned.m8n8.x4.trans.shared.b16 {%0,%1,%2,%3}, [%4];"
        : "=r"(r[0]), "=r"(r[1]), "=r"(r[2]), "=r"(r[3]) : "r"(saddr));
}
__device__ __forceinline__ void cpa16(uint32_t saddr, const void* g){
    asm volatile("cp.async.ca.shared.global [%0], [%1], 16;" :: "r"(saddr), "l"(g));
}
__device__ __forceinline__ void cpa_commit(){ asm volatile("cp.async.commit_group;"); }
__device__ __forceinline__ void cpa_wait0(){ asm volatile("cp.async.wait_group 0;"); }
__device__ __forceinline__ void cpa_wait1(){ asm volatile("cp.async.wait_group 1;"); }
__device__ __forceinline__ uint32_t ph2(float lo, float hi){
    __half2 t = __floats2half2_rn(lo, hi);
    return *(uint32_t*)&t;
}

// ------------------------------------------------------------------
// Fused fp32 -> fp16 pre-round: one launch for x + 4 weights.
// 12 chunks of 262144 float4 on blockIdx.y; 2 float4 per thread (ILP 2).
// ------------------------------------------------------------------
#define CVT_CH 262144   // float4 per chunk (= 1M floats)

__global__ void __launch_bounds__(256) cvt_all(
    const float4* __restrict__ x,
    const float4* __restrict__ Wq, const float4* __restrict__ Wk,
    const float4* __restrict__ Wv, const float4* __restrict__ Wo,
    uint2* __restrict__ xc,
    uint2* __restrict__ wq, uint2* __restrict__ wk,
    uint2* __restrict__ wv, uint2* __restrict__ wo)
{
    const int c = blockIdx.y;
    const float4* s; uint2* d;
    if (c < 8){ s = x + (size_t)c*CVT_CH; d = xc + (size_t)c*CVT_CH; }
    else if (c == 8){ s = Wq; d = wq; }
    else if (c == 9){ s = Wk; d = wk; }
    else if (c == 10){ s = Wv; d = wv; }
    else { s = Wo; d = wo; }

    int i0 = blockIdx.x*256 + threadIdx.x;
    int i1 = i0 + CVT_CH/2;
    float4 v0 = s[i0];
    float4 v1 = s[i1];
    uint2 o0, o1;
    o0.x = ph2(v0.x, v0.y); o0.y = ph2(v0.z, v0.w);
    o1.x = ph2(v1.x, v1.y); o1.y = ph2(v1.z, v1.w);
    d[i0] = o0;
    d[i1] = o1;
}

// ------------------------------------------------------------------
// fp16 GEMM: C[M,N] = A[M,K] @ W[N,K]^T (+bias). M=8192, N=K=1024.
// Block 128(m) x 128(n), BK=64 halves, 128 thr (4 warps 2m x 2n),
// warp tile 64x64 -> 8 ldsm feed 32 MMAs (128 B/MMA, 3x less LDS
// traffic than 64x32). ~185 regs/thread, 128 thr -> 2 CTAs/SM fit
// the register file AND smem. cp.async double-buffered.
// ------------------------------------------------------------------
#define RS   144                              // row stride bytes
#define GT_B (128*RS)                         // 18432 per operand tile
#define GSTG (2*GT_B)                         // 36864
#define GEMM_SMEM (2*GSTG)                    // 73728

__device__ __forceinline__ void gemm_body(
    const __half* __restrict__ A, const __half* __restrict__ W,
    const float* __restrict__ bias, void* __restrict__ C, int out_half)
{
    extern __shared__ uint32_t sh[];
    const uint32_t sbase = (uint32_t)__cvta_generic_to_shared(sh);

    const int tid  = threadIdx.x;
    const int lane = tid & 31, g = lane >> 2, tg = lane & 3;
    const int wid  = tid >> 5;                // 0..3
    const int wm   = (wid & 1) * 64;
    const int wn   = (wid >> 1) * 64;
    const int bm   = blockIdx.y * 128;
    const int bn   = blockIdx.x * 128;

    const int alr = lane & 15;
    const int alk = (lane >> 4) * 16;

    const __half* Ag = A + (size_t)bm*EMB;
    const __half* Wg = W + (size_t)bn*EMB;

    float acc[4][8][4];
#pragma unroll
    for (int mi = 0; mi < 4; mi++)
#pragma unroll
        for (int t = 0; t < 8; t++)
#pragma unroll
            for (int j = 0; j < 4; j++) acc[mi][t][j] = 0.f;

    auto stage = [&](int kt, int s){
        const uint32_t sa = sbase + (uint32_t)s*GSTG;
        const uint32_t sb = sa + GT_B;
#pragma unroll
        for (int i = 0; i < 8; i++){           // A: 128 rows x 8 chunks
            int id = tid + i*128, r = id >> 3, c = id & 7;
            cpa16(sa + r*RS + c*16, Ag + (size_t)r*EMB + kt*64 + c*8);
        }
#pragma unroll
        for (int i = 0; i < 8; i++){           // B: 128 rows x 8 chunks
            int id = tid + i*128, r = id >> 3, c = id & 7;
            cpa16(sb + r*RS + c*16, Wg + (size_t)r*EMB + kt*64 + c*8);
        }
        cpa_commit();
    };

    stage(0, 0);
    stage(1, 1);

    const int nk = EMB/64;   // 16
    for (int kt = 0; kt < nk; kt++){
        const int s = kt & 1;
        if (kt + 1 < nk) cpa_wait1(); else cpa_wait0();
        __syncthreads();
        const uint32_t sa = sbase + (uint32_t)s*GSTG;
        const uint32_t sb = sa + GT_B;
#pragma unroll
        for (int kk = 0; kk < 4; kk++){        // 4 x k16
            uint32_t af[4][4], bf[4][4];
#pragma unroll
            for (int mi = 0; mi < 4; mi++)
                ldsm4(af[mi], sa + (wm + mi*16 + alr)*RS + kk*32 + alk);
#pragma unroll
            for (int p = 0; p < 4; p++)
                ldsm4(bf[p], sb + (wn + p*16 + alr)*RS + kk*32 + alk);
#pragma unroll
            for (int mi = 0; mi < 4; mi++)
#pragma unroll
                for (int p = 0; p < 4; p++){
                    mma16(acc[mi][2*p],   af[mi], bf[p][0], bf[p][2]);
                    mma16(acc[mi][2*p+1], af[mi], bf[p][1], bf[p][3]);
                }
        }
        __syncthreads();
        if (kt + 2 < nk) stage(kt + 2, s);
    }

    // epilogue
#pragma unroll
    for (int mi = 0; mi < 4; mi++){
#pragma unroll
        for (int t = 0; t < 8; t++){
            int col  = bn + wn + t*8 + 2*tg;
            int row0 = bm + wm + mi*16 + g;
            if (out_half){
                __half2 h0 = __floats2half2_rn(acc[mi][t][0], acc[mi][t][1]);
                __half2 h1 = __floats2half2_rn(acc[mi][t][2], acc[mi][t][3]);
                *(__half2*)((__half*)C + (size_t)row0      *EMB + col) = h0;
                *(__half2*)((__half*)C + (size_t)(row0 + 8)*EMB + col) = h1;
            } else {
                float b0 = bias ? bias[col]   : 0.f;
                float b1 = bias ? bias[col+1] : 0.f;
                float2 v0 = make_float2(acc[mi][t][0] + b0, acc[mi][t][1] + b1);
                float2 v1 = make_float2(acc[mi][t][2] + b0, acc[mi][t][3] + b1);
                *(float2*)((float*)C + (size_t)row0      *EMB + col) = v0;
                *(float2*)((float*)C + (size_t)(row0 + 8)*EMB + col) = v1;
            }
        }
    }
}

__global__ void __launch_bounds__(128, 2) gemm_qkv(
    const __half* __restrict__ x,
    const __half* __restrict__ Wq, const __half* __restrict__ Wk,
    const __half* __restrict__ Wv,
    __half* __restrict__ q, __half* __restrict__ k, __half* __restrict__ v)
{
    const __half* W = (blockIdx.z == 0) ? Wq : (blockIdx.z == 1) ? Wk : Wv;
    __half*       C = (blockIdx.z == 0) ? q  : (blockIdx.z == 1) ? k  : v;
    gemm_body(x, W, nullptr, C, 1);
}
__global__ void __launch_bounds__(128, 2) gemm_out(
    const __half* __restrict__ A, const __half* __restrict__ W,
    const float* __restrict__ bias, float* __restrict__ C)
{
    gemm_body(A, W, bias, C, 0);
}

// ------------------------------------------------------------------
// Flash attention v2 (causal) — unchanged from R13.
// grid(16, B*H), 256 threads (8 warps), q-tile 128, 16 q-rows/warp.
// Q fragments hoisted; K/V double-buffered; PV via ldmatrix.trans.
// ------------------------------------------------------------------
#define QS_B (128*RS)      // 18432
#define KS_B (64*RS)       //  9216
#define ATTN_SMEM (QS_B + 4*KS_B)   // 55296

__global__ void __launch_bounds__(256, 2) attn_kernel(
    const __half* __restrict__ Q, const __half* __restrict__ K,
    const __half* __restrict__ V, __half* __restrict__ O)
{
    extern __shared__ uint32_t dyn[];
    const uint32_t sbase = (uint32_t)__cvta_generic_to_shared(dyn);
    const uint32_t qsa = sbase;

    const int tid  = threadIdx.x;
    const int lane = tid & 31, g = lane >> 2, tg = lane & 3;
    const int wq   = tid >> 5;
    const int qt   = gridDim.x - 1 - blockIdx.x;    // heavy blocks first
    const int b    = blockIdx.y >> 4;
    const int h    = blockIdx.y & 15;
    const int qbase = qt * 128;
    const float cs = 0.125f * 1.44269504088896f;    // 1/sqrt(64)*log2(e)

    const int alr = lane & 15, alk = (lane >> 4) * 16;

    const __half* Qg = Q + (size_t)(b*SEQ + qbase)*EMB + h*64;
    const __half* Kg = K + (size_t)(b*SEQ)*EMB + h*64;
    const __half* Vg = V + (size_t)(b*SEQ)*EMB + h*64;

    auto kbuf = [&](int s){ return sbase + QS_B + (uint32_t)s*KS_B; };
    auto vbuf = [&](int s){ return sbase + QS_B + 2*KS_B + (uint32_t)s*KS_B; };

    auto load_kv = [&](int jt, int s){
        uint32_t ka = kbuf(s), va = vbuf(s);
#pragma unroll
        for (int i = 0; i < 2; i++){
            int id = tid + i*256, r = id >> 3, c = id & 7;
            cpa16(ka + r*RS + c*16, Kg + (size_t)(jt*64 + r)*EMB + c*8);
        }
#pragma unroll
        for (int i = 0; i < 2; i++){
            int id = tid + i*256, r = id >> 3, c = id & 7;
            cpa16(va + r*RS + c*16, Vg + (size_t)(jt*64 + r)*EMB + c*8);
        }
    };

    const int njt = 2*qt + 2;     // always >= 2

    // prologue: group0 = Q + kv0 ; group1 = kv1 ; retire group0, load qf
#pragma unroll
    for (int i = 0; i < 4; i++){
        int id = tid + i*256, r = id >> 3, c = id & 7;
        cpa16(qsa + r*RS + c*16, Qg + (size_t)r*EMB + c*8);
    }
    load_kv(0, 0);
    cpa_commit();
    load_kv(1, 1);
    cpa_commit();
    cpa_wait1();                 // Q + kv0 arrived (kv1 in flight)
    __syncthreads();

    uint32_t qf[4][4];           // Q A-frags, loop-invariant
#pragma unroll
    for (int ks = 0; ks < 4; ks++)
        ldsm4(qf[ks], qsa + (wq*16 + alr)*RS + ks*32 + alk);

    float m0 = -1e30f, m1 = -1e30f, l0 = 0.f, l1 = 0.f;
    float o[8][4];
#pragma unroll
    for (int t = 0; t < 8; t++)
#pragma unroll
        for (int j = 0; j < 4; j++) o[t][j] = 0.f;

    const int q0r = qbase + wq*16 + g;
    const int q1r = q0r + 8;

    for (int jt = 0; jt < njt; jt++){
        const int s = jt & 1;
        const uint32_t ka = kbuf(s), va = vbuf(s);

        // ---- S = Q @ K^T : 16 q-rows x 64 keys per warp (raw scores)
        float sacc[8][4];
#pragma unroll
        for (int t = 0; t < 8; t++)
#pragma unroll
            for (int j = 0; j < 4; j++) sacc[t][j] = 0.f;
#pragma unroll
        for (int ks = 0; ks < 4; ks++){
            uint32_t bk[4][4];
#pragma unroll
            for (int p = 0; p < 4; p++)
                ldsm4(bk[p], ka + (p*16 + alr)*RS + ks*32 + alk);
#pragma unroll
            for (int p = 0; p < 4; p++){
                mma16(sacc[2*p],   qf[ks], bk[p][0], bk[p][2]);
                mma16(sacc[2*p+1], qf[ks], bk[p][1], bk[p][3]);
            }
        }

        // ---- causal mask (raw) + online softmax (max in raw domain)
        const bool need_mask = (jt >= 2*qt);
        {
            float tm0 = -1e30f, tm1 = -1e30f;
#pragma unroll
            for (int t = 0; t < 8; t++){
                float* sc = sacc[t];
                if (need_mask){
                    int jc = jt*64 + t*8 + 2*tg;
                    if (jc     > q0r) sc[0] = -1e30f;
                    if (jc + 1 > q0r) sc[1] = -1e30f;
                    if (jc     > q1r) sc[2] = -1e30f;
                    if (jc + 1 > q1r) sc[3] = -1e30f;
                }
                tm0 = fmaxf(tm0, fmaxf(sc[0], sc[1]));
                tm1 = fmaxf(tm1, fmaxf(sc[2], sc[3]));
            }
            tm0 = fmaxf(tm0, __shfl_xor_sync(0xffffffffu, tm0, 1));
            tm0 = fmaxf(tm0, __shfl_xor_sync(0xffffffffu, tm0, 2));
            tm1 = fmaxf(tm1, __shfl_xor_sync(0xffffffffu, tm1, 1));
            tm1 = fmaxf(tm1, __shfl_xor_sync(0xffffffffu, tm1, 2));
            float mn0 = fmaxf(m0, tm0 * cs);
            float mn1 = fmaxf(m1, tm1 * cs);
            float a0  = ex2f(m0 - mn0);
            float a1  = ex2f(m1 - mn1);
            float rs0 = 0.f, rs1 = 0.f;
#pragma unroll
            for (int t = 0; t < 8; t++){
                float* sc = sacc[t];
                sc[0] = ex2f(fmaf(sc[0], cs, -mn0));
                sc[1] = ex2f(fmaf(sc[1], cs, -mn0));
                sc[2] = ex2f(fmaf(sc[2], cs, -mn1));
                sc[3] = ex2f(fmaf(sc[3], cs, -mn1));
                rs0 += sc[0] + sc[1];
                rs1 += sc[2] + sc[3];
            }
            rs0 += __shfl_xor_sync(0xffffffffu, rs0, 1);
            rs0 += __shfl_xor_sync(0xffffffffu, rs0, 2);
            rs1 += __shfl_xor_sync(0xffffffffu, rs1, 1);
            rs1 += __shfl_xor_sync(0xffffffffu, rs1, 2);
            l0 = l0*a0 + rs0;
            l1 = l1*a1 + rs1;
            m0 = mn0; m1 = mn1;
#pragma unroll
            for (int t = 0; t < 8; t++){
                o[t][0] *= a0; o[t][1] *= a0;
                o[t][2] *= a1; o[t][3] *= a1;
            }
        }

        // ---- O += P @ V : B-frags via ldmatrix.trans on row-major V
#pragma unroll
        for (int ks = 0; ks < 4; ks++){
            uint32_t av[4];
            av[0] = ph2(sacc[2*ks][0],   sacc[2*ks][1]);
            av[1] = ph2(sacc[2*ks][2],   sacc[2*ks][3]);
            av[2] = ph2(sacc[2*ks+1][0], sacc[2*ks+1][1]);
            av[3] = ph2(sacc[2*ks+1][2], sacc[2*ks+1][3]);
#pragma unroll
            for (int p = 0; p < 4; p++){
                uint32_t bv[4];
                ldsm4t(bv, va + (ks*16 + alr)*RS + p*32 + alk);
                mma16(o[2*p],   av, bv[0], bv[1]);
                mma16(o[2*p+1], av, bv[2], bv[3]);
            }
        }

        // ---- pipeline: free buffer s, prefetch jt+2, ensure jt+1 arrived
        __syncthreads();
        if (jt + 1 < njt){
            if (jt + 2 < njt){ load_kv(jt + 2, s); cpa_commit(); cpa_wait1(); }
            else             { cpa_wait0(); }
            __syncthreads();
        }
    }

    // ---- epilogue: normalize, store half (feeds final GEMM)
    {
        float i0 = 1.f / l0;
        float i1 = 1.f / l1;
        size_t r0 = (size_t)(b*SEQ + q0r);
#pragma unroll
        for (int t = 0; t < 8; t++){
            int col = h*64 + t*8 + 2*tg;
            __half2 h0 = __floats2half2_rn(o[t][0]*i0, o[t][1]*i0);
            __half2 h1 = __floats2half2_rn(o[t][2]*i1, o[t][3]*i1);
            *(__half2*)(O + r0*EMB + col)       = h0;
            *(__half2*)(O + (r0 + 8)*EMB + col) = h1;
        }
    }
}

// ------------------------------------------------------------------
extern "C" void kernel_launch(void* const* d_in, const int* in_sizes, int n_in,
                              void* d_out, int out_size)
{
    const float* x  = (const float*)d_in[0];
    const float* Wq = (const float*)d_in[1];
    const float* Wk = (const float*)d_in[2];
    const float* Wv = (const float*)d_in[3];
    const float* Wo = (const float*)d_in[4];
    const float* bo = (const float*)d_in[5];
    float* out = (float*)d_out;

    __half *q, *k, *v, *ao, *xc, *wq, *wk, *wv, *wo;
    cudaGetSymbolAddress((void**)&q,  g_q);
    cudaGetSymbolAddress((void**)&k,  g_k);
    cudaGetSymbolAddress((void**)&v,  g_v);
    cudaGetSymbolAddress((void**)&ao, g_ao);
    cudaGetSymbolAddress((void**)&xc, g_xc);
    cudaGetSymbolAddress((void**)&wq, g_wq);
    cudaGetSymbolAddress((void**)&wk, g_wk);
    cudaGetSymbolAddress((void**)&wv, g_wv);
    cudaGetSymbolAddress((void**)&wo, g_wo);

    cudaFuncSetAttribute(gemm_qkv,
                         cudaFuncAttributeMaxDynamicSharedMemorySize, GEMM_SMEM);
    cudaFuncSetAttribute(gemm_out,
                         cudaFuncAttributeMaxDynamicSharedMemorySize, GEMM_SMEM);
    cudaFuncSetAttribute(attn_kernel,
                         cudaFuncAttributeMaxDynamicSharedMemorySize, ATTN_SMEM);

    // fused fp32->fp16 pre-round (x: 8 chunks, weights: 1 chunk each)
    dim3 gc(CVT_CH/(256*2), 12);          // 512 x 12
    cvt_all<<<gc, 256>>>((const float4*)x,
                         (const float4*)Wq, (const float4*)Wk,
                         (const float4*)Wv, (const float4*)Wo,
                         (uint2*)xc, (uint2*)wq, (uint2*)wk,
                         (uint2*)wv, (uint2*)wo);

    dim3 gq(EMB/128, MR/128, 3);          // 8 x 64 x 3
    gemm_qkv<<<gq, 128, GEMM_SMEM>>>(xc, wq, wk, wv, q, k, v);

    dim3 ga(SEQ/128, NB*NH);              // 16 x 64
    attn_kernel<<<ga, 256, ATTN_SMEM>>>(q, k, v, ao);

    dim3 go(EMB/128, MR/128);             // 8 x 64
    gemm_out<<<go, 128, GEMM_SMEM>>>(ao, wo, bo, out);
}